// round 2
// baseline (speedup 1.0000x reference)
#include <cuda_runtime.h>
#include <math.h>

#define HBG 512
#define WBG 512
#define IH  128
#define IW  128
#define NC  64
#define NINST 8
#define BIGV 100000.0f

typedef unsigned long long ull;

// Scratch (device globals — allocation-free rule).
__device__ float  g_bg1[NC * HBG * WBG];
__device__ float  g_bg2[NC * HBG * WBG];
__device__ float  g_imask[NINST * IH * IW];
__device__ float  g_bgmask[HBG * WBG];
// Packed weights: [ci 64][cp 32][k 10] float2 = (w[2cp][ci][k], w[2cp+1][ci][k])
__device__ float2 g_wpk[64 * 32 * 10];

#define FMA2(d, a, b) asm("fma.rn.f32x2 %0, %1, %2, %3;" : "=l"(d) : "l"(a), "l"(b), "l"(d))

// ---------------------------------------------------------------------------
// Pre-pack OIHW weights into co-pair-interleaved float2 layout.
// ---------------------------------------------------------------------------
__global__ void prepack(const float* __restrict__ w)
{
    int idx = blockIdx.x * 256 + threadIdx.x;          // 64*32*10 = 20480
    if (idx >= 64 * 32 * 10) return;
    int k  = idx % 10;
    int cp = (idx / 10) % 32;
    int ci = idx / 320;
    float2 v = make_float2(0.f, 0.f);
    if (k < 9) {
        v.x = w[((2 * cp)     * 64 + ci) * 9 + k];
        v.y = w[((2 * cp + 1) * 64 + ci) * 9 + k];
    }
    g_wpk[idx] = v;
}

// ---------------------------------------------------------------------------
// conv 3x3 SAME, 64->64, +bias, ReLU — packed f32x2 (co-pair) version.
// Block = 256 threads = 16x16 output tile; 64 cout as 32 packed accumulators.
// ---------------------------------------------------------------------------
__global__ __launch_bounds__(256)
void conv64p(const float* __restrict__ in, const float* __restrict__ bias,
             float* __restrict__ out, int Hh, int Ww)
{
    __shared__ __align__(16) float2 s_in2[8 * 324];    // (p,p) duplicated taps
    __shared__ __align__(16) float2 s_wp [8 * 320];    // [ci][cp][k pad10]

    const int tilesX = Ww >> 4;
    const int tX = blockIdx.x % tilesX;
    const int tY = blockIdx.x / tilesX;
    const int batch = blockIdx.y;
    const int tid = threadIdx.x;
    const int px = tid & 15, py = tid >> 4;
    const int ox = (tX << 4) + px, oy = (tY << 4) + py;
    const int chanStride = Hh * Ww;
    const float* inB = in + batch * NC * chanStride;

    ull acc[32];
#pragma unroll
    for (int i = 0; i < 32; i++) acc[i] = 0ull;

    for (int cc = 0; cc < 8; cc++) {
        // input tile, 8 channels, 18x18 halo, duplicated (p,p)
        for (int idx = tid; idx < 8 * 324; idx += 256) {
            int ci = idx / 324;
            int r  = idx - ci * 324;
            int ry = r / 18, rx = r - ry * 18;
            int gy = (tY << 4) + ry - 1;
            int gx = (tX << 4) + rx - 1;
            float v = 0.f;
            if ((unsigned)gy < (unsigned)Hh && (unsigned)gx < (unsigned)Ww)
                v = inB[(cc * 8 + ci) * chanStride + gy * Ww + gx];
            s_in2[idx] = make_float2(v, v);
        }
        // packed weights for this ci-chunk (straight copy, 16B vectors)
        {
            const float4* src = reinterpret_cast<const float4*>(g_wpk + cc * 8 * 320);
            float4* dst = reinterpret_cast<float4*>(s_wp);
            for (int idx = tid; idx < 8 * 320 / 2; idx += 256) dst[idx] = src[idx];
        }
        __syncthreads();

#pragma unroll 1
        for (int ci = 0; ci < 8; ci++) {
            const float2* si = s_in2 + ci * 324 + py * 18 + px;
            ull t0 = *reinterpret_cast<const ull*>(si + 0);
            ull t1 = *reinterpret_cast<const ull*>(si + 1);
            ull t2 = *reinterpret_cast<const ull*>(si + 2);
            ull t3 = *reinterpret_cast<const ull*>(si + 18);
            ull t4 = *reinterpret_cast<const ull*>(si + 19);
            ull t5 = *reinterpret_cast<const ull*>(si + 20);
            ull t6 = *reinterpret_cast<const ull*>(si + 36);
            ull t7 = *reinterpret_cast<const ull*>(si + 37);
            ull t8 = *reinterpret_cast<const ull*>(si + 38);
            const ulonglong2* wrow =
                reinterpret_cast<const ulonglong2*>(s_wp + ci * 320);
#pragma unroll
            for (int cp = 0; cp < 32; cp++) {
                ulonglong2 wa = wrow[cp * 5 + 0];   // w0 w1
                ulonglong2 wb = wrow[cp * 5 + 1];   // w2 w3
                ulonglong2 wc = wrow[cp * 5 + 2];   // w4 w5
                ulonglong2 wd = wrow[cp * 5 + 3];   // w6 w7
                ull we = reinterpret_cast<const ull*>(wrow)[cp * 10 + 8]; // w8
                FMA2(acc[cp], t0, wa.x);
                FMA2(acc[cp], t1, wa.y);
                FMA2(acc[cp], t2, wb.x);
                FMA2(acc[cp], t3, wb.y);
                FMA2(acc[cp], t4, wc.x);
                FMA2(acc[cp], t5, wc.y);
                FMA2(acc[cp], t6, wd.x);
                FMA2(acc[cp], t7, wd.y);
                FMA2(acc[cp], t8, we);
            }
        }
        __syncthreads();
    }

    float* outB = out + batch * NC * chanStride + oy * Ww + ox;
#pragma unroll
    for (int cp = 0; cp < 32; cp++) {
        unsigned lo = (unsigned)(acc[cp] & 0xffffffffull);
        unsigned hi = (unsigned)(acc[cp] >> 32);
        float v0 = __uint_as_float(lo) + bias[2 * cp];
        float v1 = __uint_as_float(hi) + bias[2 * cp + 1];
        outB[(2 * cp)     * chanStride] = v0 > 0.f ? v0 : 0.f;
        outB[(2 * cp + 1) * chanStride] = v1 > 0.f ? v1 : 0.f;
    }
}

// ---------------------------------------------------------------------------
// conv 3x3 SAME, 64 -> 1, +bias, ReLU (mask head)
// ---------------------------------------------------------------------------
__global__ __launch_bounds__(256)
void conv1out(const float* __restrict__ in, const float* __restrict__ wgt,
              const float* __restrict__ bias, float* __restrict__ out,
              int Hh, int Ww)
{
    __shared__ float s_in[8 * 324];
    __shared__ float sw[576];

    const int tilesX = Ww >> 4;
    const int tX = blockIdx.x % tilesX;
    const int tY = blockIdx.x / tilesX;
    const int batch = blockIdx.y;
    const int tid = threadIdx.x;
    const int px = tid & 15, py = tid >> 4;
    const int ox = (tX << 4) + px, oy = (tY << 4) + py;
    const int chanStride = Hh * Ww;
    const float* inB = in + batch * NC * chanStride;

    for (int idx = tid; idx < 576; idx += 256) sw[idx] = wgt[idx];

    float acc = 0.f;
    for (int cc = 0; cc < 8; cc++) {
        for (int idx = tid; idx < 8 * 324; idx += 256) {
            int ci = idx / 324;
            int r  = idx - ci * 324;
            int ry = r / 18, rx = r - ry * 18;
            int gy = (tY << 4) + ry - 1;
            int gx = (tX << 4) + rx - 1;
            float v = 0.f;
            if ((unsigned)gy < (unsigned)Hh && (unsigned)gx < (unsigned)Ww)
                v = inB[(cc * 8 + ci) * chanStride + gy * Ww + gx];
            s_in[idx] = v;
        }
        __syncthreads();
#pragma unroll
        for (int ci = 0; ci < 8; ci++) {
            const float* si = s_in + ci * 324 + py * 18 + px;
            const float* w9 = sw + (cc * 8 + ci) * 9;
            acc += w9[0] * si[0]  + w9[1] * si[1]  + w9[2] * si[2]
                 + w9[3] * si[18] + w9[4] * si[19] + w9[5] * si[20]
                 + w9[6] * si[36] + w9[7] * si[37] + w9[8] * si[38];
        }
        __syncthreads();
    }
    float v = acc + bias[0];
    out[batch * chanStride + oy * Ww + ox] = v > 0.f ? v : 0.f;
}

// ---------------------------------------------------------------------------
// Fused resize + 9-way softmax + weighted feature sum (BOX_INFO hardcoded)
// ---------------------------------------------------------------------------
__global__ __launch_bounds__(256)
void fuse_out(const float* __restrict__ instf, const float* __restrict__ bgf,
              float* __restrict__ out)
{
    const int idx = blockIdx.x * 256 + threadIdx.x;
    const int x = idx & 511, y = idx >> 9;

    const int bl[8] = {0, 64, 128, 300, 64, 200, 32, 256};
    const int bt[8] = {0, 32, 256, 300, 128, 100, 256, 320};
    const int bw[8] = {256, 192, 320, 128, 384, 256, 160, 224};
    const int bh[8] = {256, 320, 192, 128, 256, 384, 224, 160};

    float m[8], W00[8], W01[8], W10[8], W11[8];
    int O00[8], O01[8], O10[8], O11[8];
    bool ins[8];
    bool uni = false;

#pragma unroll
    for (int i = 0; i < 8; i++) {
        int xl = x - bl[i], yt = y - bt[i];
        bool in_i = ((unsigned)xl < (unsigned)bw[i]) && ((unsigned)yt < (unsigned)bh[i]);
        ins[i] = in_i;
        uni |= in_i;
        float mi = 0.f, w00 = 0.f, w01 = 0.f, w10 = 0.f, w11 = 0.f;
        int o00 = 0, o01 = 0, o10 = 0, o11 = 0;
        if (in_i) {
            float sx = ((float)xl + 0.5f) * (128.f / (float)bw[i]) - 0.5f;
            float sy = ((float)yt + 0.5f) * (128.f / (float)bh[i]) - 0.5f;
            float fxf = floorf(sx), fyf = floorf(sy);
            float fx = sx - fxf, fy = sy - fyf;
            int x0 = (int)fxf, y0 = (int)fyf;
            int x0c = x0 < 0 ? 0 : x0;
            int x1c = (x0 + 1 > 127) ? 127 : (x0 + 1);
            int y0c = y0 < 0 ? 0 : y0;
            int y1c = (y0 + 1 > 127) ? 127 : (y0 + 1);
            o00 = y0c * 128 + x0c;  o01 = y0c * 128 + x1c;
            o10 = y1c * 128 + x0c;  o11 = y1c * 128 + x1c;
            w00 = (1.f - fx) * (1.f - fy);
            w01 = fx * (1.f - fy);
            w10 = (1.f - fx) * fy;
            w11 = fx * fy;
            const float* mp = g_imask + i * (IH * IW);
            mi = w00 * mp[o00] + w01 * mp[o01] + w10 * mp[o10] + w11 * mp[o11];
        }
        m[i] = mi;
        W00[i] = w00; W01[i] = w01; W10[i] = w10; W11[i] = w11;
        O00[i] = o00; O01[i] = o01; O10[i] = o10; O11[i] = o11;
    }

    float bgv = g_bgmask[idx] + (uni ? 0.f : BIGV);
    float mx = bgv;
#pragma unroll
    for (int i = 0; i < 8; i++) mx = fmaxf(mx, m[i]);

    float ebg = expf(bgv - mx);
    float s = ebg;
    float e[8];
#pragma unroll
    for (int i = 0; i < 8; i++) { e[i] = expf(m[i] - mx); s += e[i]; }
    float inv = 1.f / s;
    float wbg = ebg * inv;
#pragma unroll
    for (int i = 0; i < 8; i++) {
        float wi = e[i] * inv;
        W00[i] *= wi; W01[i] *= wi; W10[i] *= wi; W11[i] *= wi;
    }

    for (int c = 0; c < 64; c++) {
        float accv = wbg * bgf[(c << 18) + idx];
#pragma unroll
        for (int i = 0; i < 8; i++) {
            if (ins[i]) {
                const float* fp = instf + (((i << 6) + c) << 14);
                accv += W00[i] * fp[O00[i]] + W01[i] * fp[O01[i]]
                      + W10[i] * fp[O10[i]] + W11[i] * fp[O11[i]];
            }
        }
        out[(c << 18) + idx] = accv;
    }
}

// ---------------------------------------------------------------------------
// Launcher
// ---------------------------------------------------------------------------
extern "C" void kernel_launch(void* const* d_in, const int* in_sizes, int n_in,
                              void* d_out, int out_size)
{
    const float* instf = (const float*)d_in[0];
    const float* bgf   = (const float*)d_in[1];
    const float* iw1 = (const float*)d_in[2];
    const float* ib1 = (const float*)d_in[3];
    const float* iw2 = (const float*)d_in[4];
    const float* ib2 = (const float*)d_in[5];
    const float* iw3 = (const float*)d_in[6];
    const float* ib3 = (const float*)d_in[7];
    const float* bw1 = (const float*)d_in[8];
    const float* bb1 = (const float*)d_in[9];
    const float* bw2 = (const float*)d_in[10];
    const float* bb2 = (const float*)d_in[11];
    const float* bw3 = (const float*)d_in[12];
    const float* bb3 = (const float*)d_in[13];
    float* out = (float*)d_out;

    float *ga, *gb, *gim, *gbm;
    cudaGetSymbolAddress((void**)&ga,  g_bg1);
    cudaGetSymbolAddress((void**)&gb,  g_bg2);
    cudaGetSymbolAddress((void**)&gim, g_imask);
    cudaGetSymbolAddress((void**)&gbm, g_bgmask);

    const int PP = (64 * 32 * 10 + 255) / 256;

    // Instance branch (8 x 128x128)
    prepack <<<PP, 256>>>(iw1);
    conv64p <<<dim3(64, 8), 256>>>(instf, ib1, ga, IH, IW);
    prepack <<<PP, 256>>>(iw2);
    conv64p <<<dim3(64, 8), 256>>>(ga, ib2, gb, IH, IW);
    conv1out<<<dim3(64, 8), 256>>>(gb, iw3, ib3, gim, IH, IW);

    // Background branch (1 x 512x512)
    prepack <<<PP, 256>>>(bw1);
    conv64p <<<dim3(1024, 1), 256>>>(bgf, bb1, ga, HBG, WBG);
    prepack <<<PP, 256>>>(bw2);
    conv64p <<<dim3(1024, 1), 256>>>(ga, bb2, gb, HBG, WBG);
    conv1out<<<dim3(1024, 1), 256>>>(gb, bw3, bb3, gbm, HBG, WBG);

    // Fused resize + softmax + weighted sum
    fuse_out<<<(HBG * WBG) / 256, 256>>>(instf, bgf, out);
}

// round 3
// speedup vs baseline: 1.0821x; 1.0821x over previous
#include <cuda_runtime.h>
#include <math.h>

#define HBG 512
#define WBG 512
#define IH  128
#define IW  128
#define NC  64
#define NINST 8
#define BIGV 100000.0f

typedef unsigned long long ull;

// Scratch (device globals — allocation-free rule).
__device__ float  g_bg1[NC * HBG * WBG];
__device__ float  g_bg2[NC * HBG * WBG];
__device__ float  g_imask[NINST * IH * IW];
__device__ float  g_bgmask[HBG * WBG];
// Packed weights: [ci 64][cp 32][k 10] float2 = (w[2cp][ci][k], w[2cp+1][ci][k])
__device__ float2 g_wpk[64 * 32 * 10];

#define FMA2(d, a, b) asm("fma.rn.f32x2 %0, %1, %2, %3;" : "=l"(d) : "l"(a), "l"(b), "l"(d))

// ---------------------------------------------------------------------------
// Pre-pack OIHW weights into co-pair-interleaved float2 layout.
// ---------------------------------------------------------------------------
__global__ void prepack(const float* __restrict__ w)
{
    int idx = blockIdx.x * 256 + threadIdx.x;          // 64*32*10 = 20480
    if (idx >= 64 * 32 * 10) return;
    int k  = idx % 10;
    int cp = (idx / 10) % 32;
    int ci = idx / 320;
    float2 v = make_float2(0.f, 0.f);
    if (k < 9) {
        v.x = w[((2 * cp)     * 64 + ci) * 9 + k];
        v.y = w[((2 * cp + 1) * 64 + ci) * 9 + k];
    }
    g_wpk[idx] = v;
}

// ---------------------------------------------------------------------------
// conv 3x3 SAME, 64->64, +bias, ReLU — packed f32x2, cout-split for occupancy.
// Block = 256 threads = 16x16 pixel tile x 32 couts (blockIdx.z selects half).
// 16 packed accumulators -> ~100 regs -> 2 CTAs/SM.
// ---------------------------------------------------------------------------
__global__ __launch_bounds__(256, 2)
void conv64p2(const float* __restrict__ in, const float* __restrict__ bias,
              float* __restrict__ out, int Hh, int Ww)
{
    __shared__ __align__(16) float2 s_in2[8 * 324];    // (p,p) duplicated taps
    __shared__ __align__(16) float2 s_wp [8 * 160];    // [ci][cp16][k pad10]

    const int tilesX = Ww >> 4;
    const int tX = blockIdx.x % tilesX;
    const int tY = blockIdx.x / tilesX;
    const int batch = blockIdx.y;
    const int half = blockIdx.z;                        // 0/1: cout pairs 0-15 / 16-31
    const int tid = threadIdx.x;
    const int px = tid & 15, py = tid >> 4;
    const int ox = (tX << 4) + px, oy = (tY << 4) + py;
    const int chanStride = Hh * Ww;
    const float* inB = in + batch * NC * chanStride;

    ull acc[16];
#pragma unroll
    for (int i = 0; i < 16; i++) acc[i] = 0ull;

    for (int cc = 0; cc < 8; cc++) {
        // input tile: 8 channels, 18x18 halo, duplicated (p,p)
        for (int idx = tid; idx < 8 * 324; idx += 256) {
            int ci = idx / 324;
            int r  = idx - ci * 324;
            int ry = r / 18, rx = r - ry * 18;
            int gy = (tY << 4) + ry - 1;
            int gx = (tX << 4) + rx - 1;
            float v = 0.f;
            if ((unsigned)gy < (unsigned)Hh && (unsigned)gx < (unsigned)Ww)
                v = inB[(cc * 8 + ci) * chanStride + gy * Ww + gx];
            s_in2[idx] = make_float2(v, v);
        }
        // packed weights: this ci-chunk, this cout-half (16 pairs per ci)
        for (int idx = tid; idx < 8 * 160 / 2; idx += 256) {
            // float4 = 2 float2; source row layout [ci][cp32][k10]
            int f2 = idx * 2;
            int ci = f2 / 160;
            int r  = f2 - ci * 160;
            const float4* src = reinterpret_cast<const float4*>(
                g_wpk + (cc * 8 + ci) * 320 + half * 160 + r);
            reinterpret_cast<float4*>(s_wp)[idx] = *src;
        }
        __syncthreads();

#pragma unroll 1
        for (int ci = 0; ci < 8; ci++) {
            const float2* si = s_in2 + ci * 324 + py * 18 + px;
            ull t0 = *reinterpret_cast<const ull*>(si + 0);
            ull t1 = *reinterpret_cast<const ull*>(si + 1);
            ull t2 = *reinterpret_cast<const ull*>(si + 2);
            ull t3 = *reinterpret_cast<const ull*>(si + 18);
            ull t4 = *reinterpret_cast<const ull*>(si + 19);
            ull t5 = *reinterpret_cast<const ull*>(si + 20);
            ull t6 = *reinterpret_cast<const ull*>(si + 36);
            ull t7 = *reinterpret_cast<const ull*>(si + 37);
            ull t8 = *reinterpret_cast<const ull*>(si + 38);
            const ulonglong2* wrow =
                reinterpret_cast<const ulonglong2*>(s_wp + ci * 160);
#pragma unroll
            for (int cp = 0; cp < 16; cp++) {
                ulonglong2 wa = wrow[cp * 5 + 0];   // w0 w1
                ulonglong2 wb = wrow[cp * 5 + 1];   // w2 w3
                ulonglong2 wc = wrow[cp * 5 + 2];   // w4 w5
                ulonglong2 wd = wrow[cp * 5 + 3];   // w6 w7
                ull we = reinterpret_cast<const ull*>(wrow)[cp * 10 + 8]; // w8
                FMA2(acc[cp], t0, wa.x);
                FMA2(acc[cp], t1, wa.y);
                FMA2(acc[cp], t2, wb.x);
                FMA2(acc[cp], t3, wb.y);
                FMA2(acc[cp], t4, wc.x);
                FMA2(acc[cp], t5, wc.y);
                FMA2(acc[cp], t6, wd.x);
                FMA2(acc[cp], t7, wd.y);
                FMA2(acc[cp], t8, we);
            }
        }
        __syncthreads();
    }

    float* outB = out + batch * NC * chanStride + oy * Ww + ox;
#pragma unroll
    for (int cp = 0; cp < 16; cp++) {
        int gp = half * 16 + cp;                 // global cout pair
        unsigned lo = (unsigned)(acc[cp] & 0xffffffffull);
        unsigned hi = (unsigned)(acc[cp] >> 32);
        float v0 = __uint_as_float(lo) + bias[2 * gp];
        float v1 = __uint_as_float(hi) + bias[2 * gp + 1];
        outB[(2 * gp)     * chanStride] = v0 > 0.f ? v0 : 0.f;
        outB[(2 * gp + 1) * chanStride] = v1 > 0.f ? v1 : 0.f;
    }
}

// ---------------------------------------------------------------------------
// conv 3x3 SAME, 64 -> 1, +bias, ReLU (mask head)
// ---------------------------------------------------------------------------
__global__ __launch_bounds__(256)
void conv1out(const float* __restrict__ in, const float* __restrict__ wgt,
              const float* __restrict__ bias, float* __restrict__ out,
              int Hh, int Ww)
{
    __shared__ float s_in[8 * 324];
    __shared__ float sw[576];

    const int tilesX = Ww >> 4;
    const int tX = blockIdx.x % tilesX;
    const int tY = blockIdx.x / tilesX;
    const int batch = blockIdx.y;
    const int tid = threadIdx.x;
    const int px = tid & 15, py = tid >> 4;
    const int ox = (tX << 4) + px, oy = (tY << 4) + py;
    const int chanStride = Hh * Ww;
    const float* inB = in + batch * NC * chanStride;

    for (int idx = tid; idx < 576; idx += 256) sw[idx] = wgt[idx];

    float acc = 0.f;
    for (int cc = 0; cc < 8; cc++) {
        for (int idx = tid; idx < 8 * 324; idx += 256) {
            int ci = idx / 324;
            int r  = idx - ci * 324;
            int ry = r / 18, rx = r - ry * 18;
            int gy = (tY << 4) + ry - 1;
            int gx = (tX << 4) + rx - 1;
            float v = 0.f;
            if ((unsigned)gy < (unsigned)Hh && (unsigned)gx < (unsigned)Ww)
                v = inB[(cc * 8 + ci) * chanStride + gy * Ww + gx];
            s_in[idx] = v;
        }
        __syncthreads();
#pragma unroll
        for (int ci = 0; ci < 8; ci++) {
            const float* si = s_in + ci * 324 + py * 18 + px;
            const float* w9 = sw + (cc * 8 + ci) * 9;
            acc += w9[0] * si[0]  + w9[1] * si[1]  + w9[2] * si[2]
                 + w9[3] * si[18] + w9[4] * si[19] + w9[5] * si[20]
                 + w9[6] * si[36] + w9[7] * si[37] + w9[8] * si[38];
        }
        __syncthreads();
    }
    float v = acc + bias[0];
    out[batch * chanStride + oy * Ww + ox] = v > 0.f ? v : 0.f;
}

// ---------------------------------------------------------------------------
// Fused resize + 9-way softmax + weighted feature sum (BOX_INFO hardcoded)
// ---------------------------------------------------------------------------
__global__ __launch_bounds__(256)
void fuse_out(const float* __restrict__ instf, const float* __restrict__ bgf,
              float* __restrict__ out)
{
    const int idx = blockIdx.x * 256 + threadIdx.x;
    const int x = idx & 511, y = idx >> 9;

    const int bl[8] = {0, 64, 128, 300, 64, 200, 32, 256};
    const int bt[8] = {0, 32, 256, 300, 128, 100, 256, 320};
    const int bw[8] = {256, 192, 320, 128, 384, 256, 160, 224};
    const int bh[8] = {256, 320, 192, 128, 256, 384, 224, 160};

    float m[8], W00[8], W01[8], W10[8], W11[8];
    int O00[8], O01[8], O10[8], O11[8];
    bool ins[8];
    bool uni = false;

#pragma unroll
    for (int i = 0; i < 8; i++) {
        int xl = x - bl[i], yt = y - bt[i];
        bool in_i = ((unsigned)xl < (unsigned)bw[i]) && ((unsigned)yt < (unsigned)bh[i]);
        ins[i] = in_i;
        uni |= in_i;
        float mi = 0.f, w00 = 0.f, w01 = 0.f, w10 = 0.f, w11 = 0.f;
        int o00 = 0, o01 = 0, o10 = 0, o11 = 0;
        if (in_i) {
            float sx = ((float)xl + 0.5f) * (128.f / (float)bw[i]) - 0.5f;
            float sy = ((float)yt + 0.5f) * (128.f / (float)bh[i]) - 0.5f;
            float fxf = floorf(sx), fyf = floorf(sy);
            float fx = sx - fxf, fy = sy - fyf;
            int x0 = (int)fxf, y0 = (int)fyf;
            int x0c = x0 < 0 ? 0 : x0;
            int x1c = (x0 + 1 > 127) ? 127 : (x0 + 1);
            int y0c = y0 < 0 ? 0 : y0;
            int y1c = (y0 + 1 > 127) ? 127 : (y0 + 1);
            o00 = y0c * 128 + x0c;  o01 = y0c * 128 + x1c;
            o10 = y1c * 128 + x0c;  o11 = y1c * 128 + x1c;
            w00 = (1.f - fx) * (1.f - fy);
            w01 = fx * (1.f - fy);
            w10 = (1.f - fx) * fy;
            w11 = fx * fy;
            const float* mp = g_imask + i * (IH * IW);
            mi = w00 * mp[o00] + w01 * mp[o01] + w10 * mp[o10] + w11 * mp[o11];
        }
        m[i] = mi;
        W00[i] = w00; W01[i] = w01; W10[i] = w10; W11[i] = w11;
        O00[i] = o00; O01[i] = o01; O10[i] = o10; O11[i] = o11;
    }

    float bgv = g_bgmask[idx] + (uni ? 0.f : BIGV);
    float mx = bgv;
#pragma unroll
    for (int i = 0; i < 8; i++) mx = fmaxf(mx, m[i]);

    float ebg = expf(bgv - mx);
    float s = ebg;
    float e[8];
#pragma unroll
    for (int i = 0; i < 8; i++) { e[i] = expf(m[i] - mx); s += e[i]; }
    float inv = 1.f / s;
    float wbg = ebg * inv;
#pragma unroll
    for (int i = 0; i < 8; i++) {
        float wi = e[i] * inv;
        W00[i] *= wi; W01[i] *= wi; W10[i] *= wi; W11[i] *= wi;
    }

    for (int c = 0; c < 64; c++) {
        float accv = wbg * bgf[(c << 18) + idx];
#pragma unroll
        for (int i = 0; i < 8; i++) {
            if (ins[i]) {
                const float* fp = instf + (((i << 6) + c) << 14);
                accv += W00[i] * fp[O00[i]] + W01[i] * fp[O01[i]]
                      + W10[i] * fp[O10[i]] + W11[i] * fp[O11[i]];
            }
        }
        out[(c << 18) + idx] = accv;
    }
}

// ---------------------------------------------------------------------------
// Launcher
// ---------------------------------------------------------------------------
extern "C" void kernel_launch(void* const* d_in, const int* in_sizes, int n_in,
                              void* d_out, int out_size)
{
    const float* instf = (const float*)d_in[0];
    const float* bgf   = (const float*)d_in[1];
    const float* iw1 = (const float*)d_in[2];
    const float* ib1 = (const float*)d_in[3];
    const float* iw2 = (const float*)d_in[4];
    const float* ib2 = (const float*)d_in[5];
    const float* iw3 = (const float*)d_in[6];
    const float* ib3 = (const float*)d_in[7];
    const float* bw1 = (const float*)d_in[8];
    const float* bb1 = (const float*)d_in[9];
    const float* bw2 = (const float*)d_in[10];
    const float* bb2 = (const float*)d_in[11];
    const float* bw3 = (const float*)d_in[12];
    const float* bb3 = (const float*)d_in[13];
    float* out = (float*)d_out;

    float *ga, *gb, *gim, *gbm;
    cudaGetSymbolAddress((void**)&ga,  g_bg1);
    cudaGetSymbolAddress((void**)&gb,  g_bg2);
    cudaGetSymbolAddress((void**)&gim, g_imask);
    cudaGetSymbolAddress((void**)&gbm, g_bgmask);

    const int PP = (64 * 32 * 10 + 255) / 256;

    // Instance branch (8 x 128x128)
    prepack <<<PP, 256>>>(iw1);
    conv64p2<<<dim3(64, 8, 2), 256>>>(instf, ib1, ga, IH, IW);
    prepack <<<PP, 256>>>(iw2);
    conv64p2<<<dim3(64, 8, 2), 256>>>(ga, ib2, gb, IH, IW);
    conv1out<<<dim3(64, 8), 256>>>(gb, iw3, ib3, gim, IH, IW);

    // Background branch (1 x 512x512)
    prepack <<<PP, 256>>>(bw1);
    conv64p2<<<dim3(1024, 1, 2), 256>>>(bgf, bb1, ga, HBG, WBG);
    prepack <<<PP, 256>>>(bw2);
    conv64p2<<<dim3(1024, 1, 2), 256>>>(ga, bb2, gb, HBG, WBG);
    conv1out<<<dim3(1024, 1), 256>>>(gb, bw3, bb3, gbm, HBG, WBG);

    // Fused resize + softmax + weighted sum
    fuse_out<<<(HBG * WBG) / 256, 256>>>(instf, bgf, out);
}

// round 4
// speedup vs baseline: 1.1905x; 1.1002x over previous
#include <cuda_runtime.h>
#include <math.h>

#define HBG 512
#define WBG 512
#define HW  (HBG * WBG)
#define IH  128
#define IW  128
#define NC  64
#define NINST 8
#define BIGV 100000.0f

typedef unsigned long long ull;

// Scratch (device globals — allocation-free rule).
__device__ float  g_bg1[NC * HBG * WBG];      // conv ping; later: htmp slabs
__device__ float  g_bg2[NC * HBG * WBG];      // conv pong
__device__ float  g_imask[NINST * IH * IW];
__device__ float  g_bgmask[HBG * WBG];
__device__ float  g_wf[9 * HW];               // softmax weight fields
__device__ float2 g_wpk[64 * 32 * 10];

#define FMA2(d, a, b) asm("fma.rn.f32x2 %0, %1, %2, %3;" : "=l"(d) : "l"(a), "l"(b), "l"(d))

// Box constants (compile-time from BOX_INFO)
__device__ __constant__ int   cL[8]  = {0, 64, 128, 300, 64, 200, 32, 256};
__device__ __constant__ int   cT[8]  = {0, 32, 256, 300, 128, 100, 256, 320};
__device__ __constant__ int   cBW[8] = {256, 192, 320, 128, 384, 256, 160, 224};
__device__ __constant__ int   cBH[8] = {256, 320, 192, 128, 256, 384, 224, 160};
// htmp packed offsets (floats): cumsum of bw*128*64
__device__ __constant__ int   cHOFF[8] = {0, 2097152, 3670016, 6291456,
                                          7340032, 10485760, 12582912, 13893632};

// ---------------------------------------------------------------------------
// Pre-pack OIHW weights into co-pair-interleaved float2 layout.
// ---------------------------------------------------------------------------
__global__ void prepack(const float* __restrict__ w)
{
    int idx = blockIdx.x * 256 + threadIdx.x;
    if (idx >= 64 * 32 * 10) return;
    int k  = idx % 10;
    int cp = (idx / 10) % 32;
    int ci = idx / 320;
    float2 v = make_float2(0.f, 0.f);
    if (k < 9) {
        v.x = w[((2 * cp)     * 64 + ci) * 9 + k];
        v.y = w[((2 * cp + 1) * 64 + ci) * 9 + k];
    }
    g_wpk[idx] = v;
}

// ---------------------------------------------------------------------------
// conv 3x3 SAME, 64->64, +bias, ReLU — packed f32x2, cout-split (unchanged R3)
// ---------------------------------------------------------------------------
__global__ __launch_bounds__(256, 2)
void conv64p2(const float* __restrict__ in, const float* __restrict__ bias,
              float* __restrict__ out, int Hh, int Ww)
{
    __shared__ __align__(16) float2 s_in2[8 * 324];
    __shared__ __align__(16) float2 s_wp [8 * 160];

    const int tilesX = Ww >> 4;
    const int tX = blockIdx.x % tilesX;
    const int tY = blockIdx.x / tilesX;
    const int batch = blockIdx.y;
    const int half = blockIdx.z;
    const int tid = threadIdx.x;
    const int px = tid & 15, py = tid >> 4;
    const int ox = (tX << 4) + px, oy = (tY << 4) + py;
    const int chanStride = Hh * Ww;
    const float* inB = in + batch * NC * chanStride;

    ull acc[16];
#pragma unroll
    for (int i = 0; i < 16; i++) acc[i] = 0ull;

    for (int cc = 0; cc < 8; cc++) {
        for (int idx = tid; idx < 8 * 324; idx += 256) {
            int ci = idx / 324;
            int r  = idx - ci * 324;
            int ry = r / 18, rx = r - ry * 18;
            int gy = (tY << 4) + ry - 1;
            int gx = (tX << 4) + rx - 1;
            float v = 0.f;
            if ((unsigned)gy < (unsigned)Hh && (unsigned)gx < (unsigned)Ww)
                v = inB[(cc * 8 + ci) * chanStride + gy * Ww + gx];
            s_in2[idx] = make_float2(v, v);
        }
        for (int idx = tid; idx < 8 * 160 / 2; idx += 256) {
            int f2 = idx * 2;
            int ci = f2 / 160;
            int r  = f2 - ci * 160;
            const float4* src = reinterpret_cast<const float4*>(
                g_wpk + (cc * 8 + ci) * 320 + half * 160 + r);
            reinterpret_cast<float4*>(s_wp)[idx] = *src;
        }
        __syncthreads();

#pragma unroll 1
        for (int ci = 0; ci < 8; ci++) {
            const float2* si = s_in2 + ci * 324 + py * 18 + px;
            ull t0 = *reinterpret_cast<const ull*>(si + 0);
            ull t1 = *reinterpret_cast<const ull*>(si + 1);
            ull t2 = *reinterpret_cast<const ull*>(si + 2);
            ull t3 = *reinterpret_cast<const ull*>(si + 18);
            ull t4 = *reinterpret_cast<const ull*>(si + 19);
            ull t5 = *reinterpret_cast<const ull*>(si + 20);
            ull t6 = *reinterpret_cast<const ull*>(si + 36);
            ull t7 = *reinterpret_cast<const ull*>(si + 37);
            ull t8 = *reinterpret_cast<const ull*>(si + 38);
            const ulonglong2* wrow =
                reinterpret_cast<const ulonglong2*>(s_wp + ci * 160);
#pragma unroll
            for (int cp = 0; cp < 16; cp++) {
                ulonglong2 wa = wrow[cp * 5 + 0];
                ulonglong2 wb = wrow[cp * 5 + 1];
                ulonglong2 wc = wrow[cp * 5 + 2];
                ulonglong2 wd = wrow[cp * 5 + 3];
                ull we = reinterpret_cast<const ull*>(wrow)[cp * 10 + 8];
                FMA2(acc[cp], t0, wa.x);
                FMA2(acc[cp], t1, wa.y);
                FMA2(acc[cp], t2, wb.x);
                FMA2(acc[cp], t3, wb.y);
                FMA2(acc[cp], t4, wc.x);
                FMA2(acc[cp], t5, wc.y);
                FMA2(acc[cp], t6, wd.x);
                FMA2(acc[cp], t7, wd.y);
                FMA2(acc[cp], t8, we);
            }
        }
        __syncthreads();
    }

    float* outB = out + batch * NC * chanStride + oy * Ww + ox;
#pragma unroll
    for (int cp = 0; cp < 16; cp++) {
        int gp = half * 16 + cp;
        unsigned lo = (unsigned)(acc[cp] & 0xffffffffull);
        unsigned hi = (unsigned)(acc[cp] >> 32);
        float v0 = __uint_as_float(lo) + bias[2 * gp];
        float v1 = __uint_as_float(hi) + bias[2 * gp + 1];
        outB[(2 * gp)     * chanStride] = v0 > 0.f ? v0 : 0.f;
        outB[(2 * gp + 1) * chanStride] = v1 > 0.f ? v1 : 0.f;
    }
}

// ---------------------------------------------------------------------------
// conv 3x3 SAME, 64 -> 1, +bias, ReLU (mask head) — unchanged
// ---------------------------------------------------------------------------
__global__ __launch_bounds__(256)
void conv1out(const float* __restrict__ in, const float* __restrict__ wgt,
              const float* __restrict__ bias, float* __restrict__ out,
              int Hh, int Ww)
{
    __shared__ float s_in[8 * 324];
    __shared__ float sw[576];

    const int tilesX = Ww >> 4;
    const int tX = blockIdx.x % tilesX;
    const int tY = blockIdx.x / tilesX;
    const int batch = blockIdx.y;
    const int tid = threadIdx.x;
    const int px = tid & 15, py = tid >> 4;
    const int ox = (tX << 4) + px, oy = (tY << 4) + py;
    const int chanStride = Hh * Ww;
    const float* inB = in + batch * NC * chanStride;

    for (int idx = tid; idx < 576; idx += 256) sw[idx] = wgt[idx];

    float acc = 0.f;
    for (int cc = 0; cc < 8; cc++) {
        for (int idx = tid; idx < 8 * 324; idx += 256) {
            int ci = idx / 324;
            int r  = idx - ci * 324;
            int ry = r / 18, rx = r - ry * 18;
            int gy = (tY << 4) + ry - 1;
            int gx = (tX << 4) + rx - 1;
            float v = 0.f;
            if ((unsigned)gy < (unsigned)Hh && (unsigned)gx < (unsigned)Ww)
                v = inB[(cc * 8 + ci) * chanStride + gy * Ww + gx];
            s_in[idx] = v;
        }
        __syncthreads();
#pragma unroll
        for (int ci = 0; ci < 8; ci++) {
            const float* si = s_in + ci * 324 + py * 18 + px;
            const float* w9 = sw + (cc * 8 + ci) * 9;
            acc += w9[0] * si[0]  + w9[1] * si[1]  + w9[2] * si[2]
                 + w9[3] * si[18] + w9[4] * si[19] + w9[5] * si[20]
                 + w9[6] * si[36] + w9[7] * si[37] + w9[8] * si[38];
        }
        __syncthreads();
    }
    float v = acc + bias[0];
    out[batch * chanStride + oy * Ww + ox] = v > 0.f ? v : 0.f;
}

// ---------------------------------------------------------------------------
// Stage 1: per-pixel softmax weight fields  g_wf[i][HW] (i=0..7 inst, 8=bg)
// One thread handles 4 consecutive pixels -> STG.128 per field.
// ---------------------------------------------------------------------------
__global__ __launch_bounds__(256)
void wfield_k()
{
    const int p4 = blockIdx.x * 256 + threadIdx.x;   // 0..65535
    const int base = p4 * 4;
    const int y = base >> 9;
    const int xb = base & 511;

    float4 wv[9];

#pragma unroll
    for (int j = 0; j < 4; j++) {
        const int x = xb + j;
        float m[8];
        bool uni = false;
        bool ins[8];
#pragma unroll
        for (int i = 0; i < 8; i++) {
            int xl = x - cL[i], yt = y - cT[i];
            bool in_i = ((unsigned)xl < (unsigned)cBW[i]) &&
                        ((unsigned)yt < (unsigned)cBH[i]);
            ins[i] = in_i;
            uni |= in_i;
            float mi = 0.f;
            if (in_i) {
                float sx = ((float)xl + 0.5f) * (128.f / (float)cBW[i]) - 0.5f;
                float sy = ((float)yt + 0.5f) * (128.f / (float)cBH[i]) - 0.5f;
                float fxf = floorf(sx), fyf = floorf(sy);
                float fx = sx - fxf, fy = sy - fyf;
                int x0 = (int)fxf, y0 = (int)fyf;
                int x0c = x0 < 0 ? 0 : x0;
                int x1c = (x0 + 1 > 127) ? 127 : (x0 + 1);
                int y0c = y0 < 0 ? 0 : y0;
                int y1c = (y0 + 1 > 127) ? 127 : (y0 + 1);
                const float* mp = g_imask + i * (IH * IW);
                float v00 = mp[y0c * 128 + x0c], v01 = mp[y0c * 128 + x1c];
                float v10 = mp[y1c * 128 + x0c], v11 = mp[y1c * 128 + x1c];
                mi = (1.f - fx) * (1.f - fy) * v00 + fx * (1.f - fy) * v01
                   + (1.f - fx) * fy * v10 + fx * fy * v11;
            }
            m[i] = mi;
        }
        float bgv = g_bgmask[base + j] + (uni ? 0.f : BIGV);
        float mx = bgv;
#pragma unroll
        for (int i = 0; i < 8; i++) mx = fmaxf(mx, m[i]);
        float ebg = expf(bgv - mx);
        float s = ebg;
        float e[8];
#pragma unroll
        for (int i = 0; i < 8; i++) { e[i] = ins[i] ? expf(m[i] - mx) : expf(-mx); s += e[i]; }
        float inv = 1.f / s;
        float* c0 = &wv[0].x;
#pragma unroll
        for (int i = 0; i < 8; i++) (&wv[i].x)[j] = e[i] * inv;
        (&wv[8].x)[j] = ebg * inv;
        (void)c0;
    }

#pragma unroll
    for (int i = 0; i < 9; i++)
        reinterpret_cast<float4*>(g_wf + i * HW)[p4] = wv[i];
}

// ---------------------------------------------------------------------------
// Stage 2: horizontal bilinear resize of one instance's 64-ch feature:
// 128x128 -> 128 rows x bw cols, into packed htmp slab (g_bg1 + HOFF).
// One block per (c, sy); source row staged in smem; 4 outputs per thread.
// ---------------------------------------------------------------------------
__global__ __launch_bounds__(128)
void hresize_k(const float* __restrict__ instf, int inst, int bw, float scale)
{
    __shared__ float srow[128];
    const int c  = blockIdx.x >> 7;        // 0..63
    const int sy = blockIdx.x & 127;       // 0..127
    const int tid = threadIdx.x;

    const float* src = instf + ((inst * 64 + c) * 128 + sy) * 128;
    if (tid < 32)
        reinterpret_cast<float4*>(srow)[tid] =
            reinterpret_cast<const float4*>(src)[tid];
    __syncthreads();

    float* dst = g_bg1 + cHOFF[inst] + (c * 128 + sy) * bw;
    const int nx = bw >> 2;
    for (int xg = tid; xg < nx; xg += 128) {
        float4 o;
#pragma unroll
        for (int j = 0; j < 4; j++) {
            int x = xg * 4 + j;
            float sx = ((float)x + 0.5f) * scale - 0.5f;
            float fxf = floorf(sx);
            float fx = sx - fxf;
            int x0 = (int)fxf;
            int x0c = x0 < 0 ? 0 : x0;
            int x1c = (x0 + 1 > 127) ? 127 : (x0 + 1);
            (&o.x)[j] = (1.f - fx) * srow[x0c] + fx * srow[x1c];
        }
        reinterpret_cast<float4*>(dst)[xg] = o;
    }
}

// ---------------------------------------------------------------------------
// Stage 3: out[c][px] = wbg*bg + sum_i wi * vlerp(htmp_i).  4 px per thread,
// all loads are aligned float4 (box l and bw are all multiples of 4).
// ---------------------------------------------------------------------------
__global__ __launch_bounds__(256)
void gather3(const float* __restrict__ bgf, float* __restrict__ out)
{
    const int gid = blockIdx.x * 256 + threadIdx.x;  // 64 * 65536
    const int c  = gid >> 16;
    const int p4 = gid & 65535;
    const int base = p4 * 4;
    const int y = base >> 9;
    const int xb = base & 511;

    float4 bg4  = reinterpret_cast<const float4*>(bgf + c * HW)[p4];
    float4 wbg4 = reinterpret_cast<const float4*>(g_wf + 8 * HW)[p4];
    float4 acc;
    acc.x = wbg4.x * bg4.x;
    acc.y = wbg4.y * bg4.y;
    acc.z = wbg4.z * bg4.z;
    acc.w = wbg4.w * bg4.w;

#pragma unroll
    for (int i = 0; i < 8; i++) {
        int xl = xb - cL[i], yt = y - cT[i];
        if (((unsigned)xl < (unsigned)cBW[i]) && ((unsigned)yt < (unsigned)cBH[i])) {
            float4 wi4 = reinterpret_cast<const float4*>(g_wf + i * HW)[p4];
            float sy = ((float)yt + 0.5f) * (128.f / (float)cBH[i]) - 0.5f;
            float fyf = floorf(sy);
            float fy = sy - fyf;
            int y0 = (int)fyf;
            int y0c = y0 < 0 ? 0 : y0;
            int y1c = (y0 + 1 > 127) ? 127 : (y0 + 1);
            const float* hb = g_bg1 + cHOFF[i] + c * 128 * cBW[i];
            float4 r0 = *reinterpret_cast<const float4*>(hb + y0c * cBW[i] + xl);
            float4 r1 = *reinterpret_cast<const float4*>(hb + y1c * cBW[i] + xl);
            float g0 = 1.f - fy;
            acc.x += wi4.x * (g0 * r0.x + fy * r1.x);
            acc.y += wi4.y * (g0 * r0.y + fy * r1.y);
            acc.z += wi4.z * (g0 * r0.z + fy * r1.z);
            acc.w += wi4.w * (g0 * r0.w + fy * r1.w);
        }
    }

    reinterpret_cast<float4*>(out + c * HW)[p4] = acc;
}

// ---------------------------------------------------------------------------
// Launcher
// ---------------------------------------------------------------------------
extern "C" void kernel_launch(void* const* d_in, const int* in_sizes, int n_in,
                              void* d_out, int out_size)
{
    const float* instf = (const float*)d_in[0];
    const float* bgf   = (const float*)d_in[1];
    const float* iw1 = (const float*)d_in[2];
    const float* ib1 = (const float*)d_in[3];
    const float* iw2 = (const float*)d_in[4];
    const float* ib2 = (const float*)d_in[5];
    const float* iw3 = (const float*)d_in[6];
    const float* ib3 = (const float*)d_in[7];
    const float* bw1 = (const float*)d_in[8];
    const float* bb1 = (const float*)d_in[9];
    const float* bw2 = (const float*)d_in[10];
    const float* bb2 = (const float*)d_in[11];
    const float* bw3 = (const float*)d_in[12];
    const float* bb3 = (const float*)d_in[13];
    float* out = (float*)d_out;

    float *ga, *gb, *gim, *gbm;
    cudaGetSymbolAddress((void**)&ga,  g_bg1);
    cudaGetSymbolAddress((void**)&gb,  g_bg2);
    cudaGetSymbolAddress((void**)&gim, g_imask);
    cudaGetSymbolAddress((void**)&gbm, g_bgmask);

    const int PP = (64 * 32 * 10 + 255) / 256;

    // Instance branch (8 x 128x128) — uses ga/gb scratch
    prepack <<<PP, 256>>>(iw1);
    conv64p2<<<dim3(64, 8, 2), 256>>>(instf, ib1, ga, IH, IW);
    prepack <<<PP, 256>>>(iw2);
    conv64p2<<<dim3(64, 8, 2), 256>>>(ga, ib2, gb, IH, IW);
    conv1out<<<dim3(64, 8), 256>>>(gb, iw3, ib3, gim, IH, IW);

    // Background branch (1 x 512x512)
    prepack <<<PP, 256>>>(bw1);
    conv64p2<<<dim3(1024, 1, 2), 256>>>(bgf, bb1, ga, HBG, WBG);
    prepack <<<PP, 256>>>(bw2);
    conv64p2<<<dim3(1024, 1, 2), 256>>>(ga, bb2, gb, HBG, WBG);
    conv1out<<<dim3(1024, 1), 256>>>(gb, bw3, bb3, gbm, HBG, WBG);

    // Stage 1: softmax weight fields (needs g_imask, g_bgmask)
    wfield_k<<<HW / 4 / 256, 256>>>();

    // Stage 2: horizontal resize of instance features into g_bg1 slabs
    // (g_bg1 is dead after the second bg conv read it)
    const int hbw[8] = {256, 192, 320, 128, 384, 256, 160, 224};
    for (int i = 0; i < 8; i++)
        hresize_k<<<64 * 128, 128>>>(instf, i, hbw[i], 128.f / (float)hbw[i]);

    // Stage 3: vertical lerp + weighted sum + bg
    gather3<<<64 * (HW / 4) / 256, 256>>>(bgf, out);
}

// round 5
// speedup vs baseline: 1.3091x; 1.0997x over previous
#include <cuda_runtime.h>
#include <math.h>

#define HBG 512
#define WBG 512
#define HW  (HBG * WBG)
#define IH  128
#define IW  128
#define NC  64
#define NINST 8
#define BIGV 100000.0f

typedef unsigned long long ull;

// Scratch (device globals — allocation-free rule).
__device__ float  g_bg1[NC * HBG * WBG];      // conv ping; later: htmp slabs
__device__ float  g_bg2[NC * HBG * WBG];      // conv pong
__device__ float  g_imask[NINST * IH * IW];
__device__ float  g_bgmask[HBG * WBG];
__device__ float  g_wf[9 * HW];               // softmax weight fields
__device__ float2 g_wpk[64 * 32 * 10];

#define FMA2(d, a, b) asm("fma.rn.f32x2 %0, %1, %2, %3;" : "=l"(d) : "l"(a), "l"(b), "l"(d))

// Box constants (compile-time from BOX_INFO)
__device__ __constant__ int   cL[8]  = {0, 64, 128, 300, 64, 200, 32, 256};
__device__ __constant__ int   cT[8]  = {0, 32, 256, 300, 128, 100, 256, 320};
__device__ __constant__ int   cBW[8] = {256, 192, 320, 128, 384, 256, 160, 224};
__device__ __constant__ int   cBH[8] = {256, 320, 192, 128, 256, 384, 224, 160};
__device__ __constant__ int   cHOFF[8] = {0, 2097152, 3670016, 6291456,
                                          7340032, 10485760, 12582912, 13893632};

// ---------------------------------------------------------------------------
// Pre-pack OIHW weights into co-pair-interleaved float2 layout.
// layout: [ci 64][cp 32][k 10], element = (w[2cp][ci][k], w[2cp+1][ci][k])
// ---------------------------------------------------------------------------
__global__ void prepack(const float* __restrict__ w)
{
    int idx = blockIdx.x * 256 + threadIdx.x;
    if (idx >= 64 * 32 * 10) return;
    int k  = idx % 10;
    int cp = (idx / 10) % 32;
    int ci = idx / 320;
    float2 v = make_float2(0.f, 0.f);
    if (k < 9) {
        v.x = w[((2 * cp)     * 64 + ci) * 9 + k];
        v.y = w[((2 * cp + 1) * 64 + ci) * 9 + k];
    }
    g_wpk[idx] = v;
}

// ---------------------------------------------------------------------------
// conv 3x3 SAME, 64->64, +bias, ReLU — f32x2 packed couts, 2 px/thread.
// Block = 256 threads, tile 16x32 px; each thread = vertical pixel pair x
// 16 couts (8 packed pairs); blockIdx.z in 0..3 selects the cout quarter.
// Weight LDS amortized over 2 px -> 4 LDS per 18 FFMA2.
// ---------------------------------------------------------------------------
__global__ __launch_bounds__(256, 2)
void conv64q(const float* __restrict__ in, const float* __restrict__ bias,
             float* __restrict__ out, int Hh, int Ww)
{
    __shared__ __align__(16) float2 s_in2[8 * 612];   // 8 ci x 34x18 halo, (p,p)
    __shared__ __align__(16) float2 s_wp [8 * 80];    // 8 ci x 8 pairs x 10

    const int tilesX = Ww >> 4;
    const int tX = blockIdx.x % tilesX;
    const int tY = blockIdx.x / tilesX;               // 32-row tiles
    const int batch = blockIdx.y;
    const int qz = blockIdx.z;                        // cout quarter 0..3
    const int tid = threadIdx.x;
    const int px  = tid & 15;
    const int pyh = tid >> 4;                         // 0..15 half-row pairs
    const int ox = (tX << 4) + px;
    const int oy0 = (tY << 5) + (pyh << 1);
    const int chanStride = Hh * Ww;
    const float* inB = in + batch * NC * chanStride;

    ull accA[8], accB[8];
#pragma unroll
    for (int i = 0; i < 8; i++) { accA[i] = 0ull; accB[i] = 0ull; }

    for (int cc = 0; cc < 8; cc++) {
        // input tile: 8 channels, 34x18 halo, duplicated (p,p)
        for (int idx = tid; idx < 8 * 612; idx += 256) {
            int ci = idx / 612;
            int r  = idx - ci * 612;
            int ry = r / 18, rx = r - ry * 18;
            int gy = (tY << 5) + ry - 1;
            int gx = (tX << 4) + rx - 1;
            float v = 0.f;
            if ((unsigned)gy < (unsigned)Hh && (unsigned)gx < (unsigned)Ww)
                v = inB[(cc * 8 + ci) * chanStride + gy * Ww + gx];
            s_in2[idx] = make_float2(v, v);
        }
        // packed weights: this ci-chunk, this cout quarter (8 pairs per ci)
        for (int idx = tid; idx < 320; idx += 256) {   // 320 float4
            int ci = idx / 40;
            int r  = idx - ci * 40;
            reinterpret_cast<float4*>(s_wp)[idx] =
                reinterpret_cast<const float4*>(g_wpk)[(cc * 8 + ci) * 160 + qz * 40 + r];
        }
        __syncthreads();

#pragma unroll 1
        for (int ci = 0; ci < 8; ci++) {
            const float2* si = s_in2 + ci * 612 + (pyh << 1) * 18 + px;
            ull t0  = *reinterpret_cast<const ull*>(si + 0);
            ull t1  = *reinterpret_cast<const ull*>(si + 1);
            ull t2  = *reinterpret_cast<const ull*>(si + 2);
            ull t3  = *reinterpret_cast<const ull*>(si + 18);
            ull t4  = *reinterpret_cast<const ull*>(si + 19);
            ull t5  = *reinterpret_cast<const ull*>(si + 20);
            ull t6  = *reinterpret_cast<const ull*>(si + 36);
            ull t7  = *reinterpret_cast<const ull*>(si + 37);
            ull t8  = *reinterpret_cast<const ull*>(si + 38);
            ull t9  = *reinterpret_cast<const ull*>(si + 54);
            ull t10 = *reinterpret_cast<const ull*>(si + 55);
            ull t11 = *reinterpret_cast<const ull*>(si + 56);
            const ulonglong2* wrow =
                reinterpret_cast<const ulonglong2*>(s_wp + ci * 80);
#pragma unroll
            for (int cp = 0; cp < 8; cp++) {
                ulonglong2 wa = wrow[cp * 5 + 0];   // w0 w1
                ulonglong2 wb = wrow[cp * 5 + 1];   // w2 w3
                ulonglong2 wc = wrow[cp * 5 + 2];   // w4 w5
                ulonglong2 wd = wrow[cp * 5 + 3];   // w6 w7
                ull we = reinterpret_cast<const ull*>(wrow)[cp * 10 + 8]; // w8
                // row oy0
                FMA2(accA[cp], t0, wa.x);
                FMA2(accA[cp], t1, wa.y);
                FMA2(accA[cp], t2, wb.x);
                FMA2(accA[cp], t3, wb.y);
                FMA2(accA[cp], t4, wc.x);
                FMA2(accA[cp], t5, wc.y);
                FMA2(accA[cp], t6, wd.x);
                FMA2(accA[cp], t7, wd.y);
                FMA2(accA[cp], t8, we);
                // row oy0+1 (shifted one row down)
                FMA2(accB[cp], t3, wa.x);
                FMA2(accB[cp], t4, wa.y);
                FMA2(accB[cp], t5, wb.x);
                FMA2(accB[cp], t6, wb.y);
                FMA2(accB[cp], t7, wc.x);
                FMA2(accB[cp], t8, wc.y);
                FMA2(accB[cp], t9, wd.x);
                FMA2(accB[cp], t10, wd.y);
                FMA2(accB[cp], t11, we);
            }
        }
        __syncthreads();
    }

    float* outB = out + batch * NC * chanStride + oy0 * Ww + ox;
#pragma unroll
    for (int cp = 0; cp < 8; cp++) {
        int gp = qz * 8 + cp;                 // global cout pair
        float b0 = bias[2 * gp], b1 = bias[2 * gp + 1];
        unsigned a_lo = (unsigned)(accA[cp] & 0xffffffffull);
        unsigned a_hi = (unsigned)(accA[cp] >> 32);
        unsigned b_lo = (unsigned)(accB[cp] & 0xffffffffull);
        unsigned b_hi = (unsigned)(accB[cp] >> 32);
        float v00 = __uint_as_float(a_lo) + b0;   // row0, cout even
        float v01 = __uint_as_float(a_hi) + b1;   // row0, cout odd
        float v10 = __uint_as_float(b_lo) + b0;   // row1, cout even
        float v11 = __uint_as_float(b_hi) + b1;   // row1, cout odd
        float* p0 = outB + (2 * gp) * chanStride;
        float* p1 = outB + (2 * gp + 1) * chanStride;
        p0[0]  = v00 > 0.f ? v00 : 0.f;
        p1[0]  = v01 > 0.f ? v01 : 0.f;
        p0[Ww] = v10 > 0.f ? v10 : 0.f;
        p1[Ww] = v11 > 0.f ? v11 : 0.f;
    }
}

// ---------------------------------------------------------------------------
// conv 3x3 SAME, 64 -> 1, +bias, ReLU (mask head)
// ---------------------------------------------------------------------------
__global__ __launch_bounds__(256)
void conv1out(const float* __restrict__ in, const float* __restrict__ wgt,
              const float* __restrict__ bias, float* __restrict__ out,
              int Hh, int Ww)
{
    __shared__ float s_in[8 * 324];
    __shared__ float sw[576];

    const int tilesX = Ww >> 4;
    const int tX = blockIdx.x % tilesX;
    const int tY = blockIdx.x / tilesX;
    const int batch = blockIdx.y;
    const int tid = threadIdx.x;
    const int px = tid & 15, py = tid >> 4;
    const int ox = (tX << 4) + px, oy = (tY << 4) + py;
    const int chanStride = Hh * Ww;
    const float* inB = in + batch * NC * chanStride;

    for (int idx = tid; idx < 576; idx += 256) sw[idx] = wgt[idx];

    float acc = 0.f;
    for (int cc = 0; cc < 8; cc++) {
        for (int idx = tid; idx < 8 * 324; idx += 256) {
            int ci = idx / 324;
            int r  = idx - ci * 324;
            int ry = r / 18, rx = r - ry * 18;
            int gy = (tY << 4) + ry - 1;
            int gx = (tX << 4) + rx - 1;
            float v = 0.f;
            if ((unsigned)gy < (unsigned)Hh && (unsigned)gx < (unsigned)Ww)
                v = inB[(cc * 8 + ci) * chanStride + gy * Ww + gx];
            s_in[idx] = v;
        }
        __syncthreads();
#pragma unroll
        for (int ci = 0; ci < 8; ci++) {
            const float* si = s_in + ci * 324 + py * 18 + px;
            const float* w9 = sw + (cc * 8 + ci) * 9;
            acc += w9[0] * si[0]  + w9[1] * si[1]  + w9[2] * si[2]
                 + w9[3] * si[18] + w9[4] * si[19] + w9[5] * si[20]
                 + w9[6] * si[36] + w9[7] * si[37] + w9[8] * si[38];
        }
        __syncthreads();
    }
    float v = acc + bias[0];
    out[batch * chanStride + oy * Ww + ox] = v > 0.f ? v : 0.f;
}

// ---------------------------------------------------------------------------
// Stage 1: per-pixel softmax weight fields  g_wf[i][HW] (i=0..7 inst, 8=bg)
// ---------------------------------------------------------------------------
__global__ __launch_bounds__(256)
void wfield_k()
{
    const int p4 = blockIdx.x * 256 + threadIdx.x;
    const int base = p4 * 4;
    const int y = base >> 9;
    const int xb = base & 511;

    float4 wv[9];

#pragma unroll
    for (int j = 0; j < 4; j++) {
        const int x = xb + j;
        float m[8];
        bool uni = false;
        bool ins[8];
#pragma unroll
        for (int i = 0; i < 8; i++) {
            int xl = x - cL[i], yt = y - cT[i];
            bool in_i = ((unsigned)xl < (unsigned)cBW[i]) &&
                        ((unsigned)yt < (unsigned)cBH[i]);
            ins[i] = in_i;
            uni |= in_i;
            float mi = 0.f;
            if (in_i) {
                float sx = ((float)xl + 0.5f) * (128.f / (float)cBW[i]) - 0.5f;
                float sy = ((float)yt + 0.5f) * (128.f / (float)cBH[i]) - 0.5f;
                float fxf = floorf(sx), fyf = floorf(sy);
                float fx = sx - fxf, fy = sy - fyf;
                int x0 = (int)fxf, y0 = (int)fyf;
                int x0c = x0 < 0 ? 0 : x0;
                int x1c = (x0 + 1 > 127) ? 127 : (x0 + 1);
                int y0c = y0 < 0 ? 0 : y0;
                int y1c = (y0 + 1 > 127) ? 127 : (y0 + 1);
                const float* mp = g_imask + i * (IH * IW);
                float v00 = mp[y0c * 128 + x0c], v01 = mp[y0c * 128 + x1c];
                float v10 = mp[y1c * 128 + x0c], v11 = mp[y1c * 128 + x1c];
                mi = (1.f - fx) * (1.f - fy) * v00 + fx * (1.f - fy) * v01
                   + (1.f - fx) * fy * v10 + fx * fy * v11;
            }
            m[i] = mi;
        }
        float bgv = g_bgmask[base + j] + (uni ? 0.f : BIGV);
        float mx = bgv;
#pragma unroll
        for (int i = 0; i < 8; i++) mx = fmaxf(mx, m[i]);
        float ebg = expf(bgv - mx);
        float s = ebg;
        float e[8];
#pragma unroll
        for (int i = 0; i < 8; i++) { e[i] = expf(m[i] - mx); s += e[i]; }
        float inv = 1.f / s;
#pragma unroll
        for (int i = 0; i < 8; i++) (&wv[i].x)[j] = e[i] * inv;
        (&wv[8].x)[j] = ebg * inv;
    }

#pragma unroll
    for (int i = 0; i < 9; i++)
        reinterpret_cast<float4*>(g_wf + i * HW)[p4] = wv[i];
}

// ---------------------------------------------------------------------------
// Stage 2: horizontal bilinear resize 128x128 -> 128 x bw per channel
// ---------------------------------------------------------------------------
__global__ __launch_bounds__(128)
void hresize_k(const float* __restrict__ instf, int inst, int bw, float scale)
{
    __shared__ float srow[128];
    const int c  = blockIdx.x >> 7;
    const int sy = blockIdx.x & 127;
    const int tid = threadIdx.x;

    const float* src = instf + ((inst * 64 + c) * 128 + sy) * 128;
    if (tid < 32)
        reinterpret_cast<float4*>(srow)[tid] =
            reinterpret_cast<const float4*>(src)[tid];
    __syncthreads();

    float* dst = g_bg1 + cHOFF[inst] + (c * 128 + sy) * bw;
    const int nx = bw >> 2;
    for (int xg = tid; xg < nx; xg += 128) {
        float4 o;
#pragma unroll
        for (int j = 0; j < 4; j++) {
            int x = xg * 4 + j;
            float sx = ((float)x + 0.5f) * scale - 0.5f;
            float fxf = floorf(sx);
            float fx = sx - fxf;
            int x0 = (int)fxf;
            int x0c = x0 < 0 ? 0 : x0;
            int x1c = (x0 + 1 > 127) ? 127 : (x0 + 1);
            (&o.x)[j] = (1.f - fx) * srow[x0c] + fx * srow[x1c];
        }
        reinterpret_cast<float4*>(dst)[xg] = o;
    }
}

// ---------------------------------------------------------------------------
// Stage 3: out[c][px] = wbg*bg + sum_i wi * vlerp(htmp_i); float4 per thread.
// ---------------------------------------------------------------------------
__global__ __launch_bounds__(256)
void gather3(const float* __restrict__ bgf, float* __restrict__ out)
{
    const int gid = blockIdx.x * 256 + threadIdx.x;
    const int c  = gid >> 16;
    const int p4 = gid & 65535;
    const int base = p4 * 4;
    const int y = base >> 9;
    const int xb = base & 511;

    float4 bg4  = reinterpret_cast<const float4*>(bgf + c * HW)[p4];
    float4 wbg4 = reinterpret_cast<const float4*>(g_wf + 8 * HW)[p4];
    float4 acc;
    acc.x = wbg4.x * bg4.x;
    acc.y = wbg4.y * bg4.y;
    acc.z = wbg4.z * bg4.z;
    acc.w = wbg4.w * bg4.w;

#pragma unroll
    for (int i = 0; i < 8; i++) {
        int xl = xb - cL[i], yt = y - cT[i];
        if (((unsigned)xl < (unsigned)cBW[i]) && ((unsigned)yt < (unsigned)cBH[i])) {
            float4 wi4 = reinterpret_cast<const float4*>(g_wf + i * HW)[p4];
            float sy = ((float)yt + 0.5f) * (128.f / (float)cBH[i]) - 0.5f;
            float fyf = floorf(sy);
            float fy = sy - fyf;
            int y0 = (int)fyf;
            int y0c = y0 < 0 ? 0 : y0;
            int y1c = (y0 + 1 > 127) ? 127 : (y0 + 1);
            const float* hb = g_bg1 + cHOFF[i] + c * 128 * cBW[i];
            float4 r0 = *reinterpret_cast<const float4*>(hb + y0c * cBW[i] + xl);
            float4 r1 = *reinterpret_cast<const float4*>(hb + y1c * cBW[i] + xl);
            float g0 = 1.f - fy;
            acc.x += wi4.x * (g0 * r0.x + fy * r1.x);
            acc.y += wi4.y * (g0 * r0.y + fy * r1.y);
            acc.z += wi4.z * (g0 * r0.z + fy * r1.z);
            acc.w += wi4.w * (g0 * r0.w + fy * r1.w);
        }
    }

    reinterpret_cast<float4*>(out + c * HW)[p4] = acc;
}

// ---------------------------------------------------------------------------
// Launcher
// ---------------------------------------------------------------------------
extern "C" void kernel_launch(void* const* d_in, const int* in_sizes, int n_in,
                              void* d_out, int out_size)
{
    const float* instf = (const float*)d_in[0];
    const float* bgf   = (const float*)d_in[1];
    const float* iw1 = (const float*)d_in[2];
    const float* ib1 = (const float*)d_in[3];
    const float* iw2 = (const float*)d_in[4];
    const float* ib2 = (const float*)d_in[5];
    const float* iw3 = (const float*)d_in[6];
    const float* ib3 = (const float*)d_in[7];
    const float* bw1 = (const float*)d_in[8];
    const float* bb1 = (const float*)d_in[9];
    const float* bw2 = (const float*)d_in[10];
    const float* bb2 = (const float*)d_in[11];
    const float* bw3 = (const float*)d_in[12];
    const float* bb3 = (const float*)d_in[13];
    float* out = (float*)d_out;

    float *ga, *gb, *gim, *gbm;
    cudaGetSymbolAddress((void**)&ga,  g_bg1);
    cudaGetSymbolAddress((void**)&gb,  g_bg2);
    cudaGetSymbolAddress((void**)&gim, g_imask);
    cudaGetSymbolAddress((void**)&gbm, g_bgmask);

    const int PP = (64 * 32 * 10 + 255) / 256;

    // Instance branch: 8 x 128x128 -> tiles 8x4=32, z=4 cout quarters
    prepack <<<PP, 256>>>(iw1);
    conv64q <<<dim3(32, 8, 4), 256>>>(instf, ib1, ga, IH, IW);
    prepack <<<PP, 256>>>(iw2);
    conv64q <<<dim3(32, 8, 4), 256>>>(ga, ib2, gb, IH, IW);
    conv1out<<<dim3(64, 8), 256>>>(gb, iw3, ib3, gim, IH, IW);

    // Background branch: 512x512 -> tiles 32x16=512, z=4
    prepack <<<PP, 256>>>(bw1);
    conv64q <<<dim3(512, 1, 4), 256>>>(bgf, bb1, ga, HBG, WBG);
    prepack <<<PP, 256>>>(bw2);
    conv64q <<<dim3(512, 1, 4), 256>>>(ga, bb2, gb, HBG, WBG);
    conv1out<<<dim3(1024, 1), 256>>>(gb, bw3, bb3, gbm, HBG, WBG);

    // Epilogue stages
    wfield_k<<<HW / 4 / 256, 256>>>();
    const int hbw[8] = {256, 192, 320, 128, 384, 256, 160, 224};
    for (int i = 0; i < 8; i++)
        hresize_k<<<64 * 128, 128>>>(instf, i, hbw[i], 128.f / (float)hbw[i]);
    gather3<<<64 * (HW / 4) / 256, 256>>>(bgf, out);
}

// round 6
// speedup vs baseline: 1.3170x; 1.0060x over previous
#include <cuda_runtime.h>
#include <math.h>

#define HBG 512
#define WBG 512
#define HW  (HBG * WBG)
#define IH  128
#define IW  128
#define NC  64
#define NINST 8
#define BIGV 100000.0f

typedef unsigned long long ull;

// Scratch (device globals — allocation-free rule).
__device__ float  g_bg1[NC * HBG * WBG];      // conv ping; later: htmp slabs
__device__ float  g_bg2[NC * HBG * WBG];      // conv pong
__device__ float  g_imask[NINST * IH * IW];
__device__ float  g_bgmask[HBG * WBG];
__device__ float  g_wf[9 * HW];               // softmax weight fields
__device__ float2 g_wpk[64 * 32 * 10];

#define FMA2(d, a, b) asm("fma.rn.f32x2 %0, %1, %2, %3;" : "=l"(d) : "l"(a), "l"(b), "l"(d))

// Box constants (compile-time from BOX_INFO)
__device__ __constant__ int   cL[8]  = {0, 64, 128, 300, 64, 200, 32, 256};
__device__ __constant__ int   cT[8]  = {0, 32, 256, 300, 128, 100, 256, 320};
__device__ __constant__ int   cBW[8] = {256, 192, 320, 128, 384, 256, 160, 224};
__device__ __constant__ int   cBH[8] = {256, 320, 192, 128, 256, 384, 224, 160};
__device__ __constant__ int   cHOFF[8] = {0, 2097152, 3670016, 6291456,
                                          7340032, 10485760, 12582912, 13893632};

// ---------------------------------------------------------------------------
// Pre-pack OIHW weights into co-pair-interleaved float2 layout.
// layout: [ci 64][cp 32][k 10], element = (w[2cp][ci][k], w[2cp+1][ci][k])
// ---------------------------------------------------------------------------
__global__ void prepack(const float* __restrict__ w)
{
    int idx = blockIdx.x * 256 + threadIdx.x;
    if (idx >= 64 * 32 * 10) return;
    int k  = idx % 10;
    int cp = (idx / 10) % 32;
    int ci = idx / 320;
    float2 v = make_float2(0.f, 0.f);
    if (k < 9) {
        v.x = w[((2 * cp)     * 64 + ci) * 9 + k];
        v.y = w[((2 * cp + 1) * 64 + ci) * 9 + k];
    }
    g_wpk[idx] = v;
}

// ---------------------------------------------------------------------------
// conv 3x3 SAME, 64->64, +bias, ReLU — f32x2 packed couts, 2 px/thread.
// Block = 256 threads, tile 16x32 px; each thread = vertical pixel pair x
// 16 couts (8 packed pairs); blockIdx.z in 0..3 selects the cout quarter.
// Weight LDS amortized over 2 px -> 4 LDS per 18 FFMA2.
// ---------------------------------------------------------------------------
__global__ __launch_bounds__(256, 2)
void conv64q(const float* __restrict__ in, const float* __restrict__ bias,
             float* __restrict__ out, int Hh, int Ww)
{
    __shared__ __align__(16) float2 s_in2[8 * 612];   // 8 ci x 34x18 halo, (p,p)
    __shared__ __align__(16) float2 s_wp [8 * 80];    // 8 ci x 8 pairs x 10

    const int tilesX = Ww >> 4;
    const int tX = blockIdx.x % tilesX;
    const int tY = blockIdx.x / tilesX;               // 32-row tiles
    const int batch = blockIdx.y;
    const int qz = blockIdx.z;                        // cout quarter 0..3
    const int tid = threadIdx.x;
    const int px  = tid & 15;
    const int pyh = tid >> 4;                         // 0..15 half-row pairs
    const int ox = (tX << 4) + px;
    const int oy0 = (tY << 5) + (pyh << 1);
    const int chanStride = Hh * Ww;
    const float* inB = in + batch * NC * chanStride;

    ull accA[8], accB[8];
#pragma unroll
    for (int i = 0; i < 8; i++) { accA[i] = 0ull; accB[i] = 0ull; }

    for (int cc = 0; cc < 8; cc++) {
        // input tile: 8 channels, 34x18 halo, duplicated (p,p)
        for (int idx = tid; idx < 8 * 612; idx += 256) {
            int ci = idx / 612;
            int r  = idx - ci * 612;
            int ry = r / 18, rx = r - ry * 18;
            int gy = (tY << 5) + ry - 1;
            int gx = (tX << 4) + rx - 1;
            float v = 0.f;
            if ((unsigned)gy < (unsigned)Hh && (unsigned)gx < (unsigned)Ww)
                v = inB[(cc * 8 + ci) * chanStride + gy * Ww + gx];
            s_in2[idx] = make_float2(v, v);
        }
        // packed weights: this ci-chunk, this cout quarter (8 pairs per ci)
        for (int idx = tid; idx < 320; idx += 256) {   // 320 float4
            int ci = idx / 40;
            int r  = idx - ci * 40;
            reinterpret_cast<float4*>(s_wp)[idx] =
                reinterpret_cast<const float4*>(g_wpk)[(cc * 8 + ci) * 160 + qz * 40 + r];
        }
        __syncthreads();

#pragma unroll 1
        for (int ci = 0; ci < 8; ci++) {
            const float2* si = s_in2 + ci * 612 + (pyh << 1) * 18 + px;
            ull t0  = *reinterpret_cast<const ull*>(si + 0);
            ull t1  = *reinterpret_cast<const ull*>(si + 1);
            ull t2  = *reinterpret_cast<const ull*>(si + 2);
            ull t3  = *reinterpret_cast<const ull*>(si + 18);
            ull t4  = *reinterpret_cast<const ull*>(si + 19);
            ull t5  = *reinterpret_cast<const ull*>(si + 20);
            ull t6  = *reinterpret_cast<const ull*>(si + 36);
            ull t7  = *reinterpret_cast<const ull*>(si + 37);
            ull t8  = *reinterpret_cast<const ull*>(si + 38);
            ull t9  = *reinterpret_cast<const ull*>(si + 54);
            ull t10 = *reinterpret_cast<const ull*>(si + 55);
            ull t11 = *reinterpret_cast<const ull*>(si + 56);
            const ulonglong2* wrow =
                reinterpret_cast<const ulonglong2*>(s_wp + ci * 80);
#pragma unroll
            for (int cp = 0; cp < 8; cp++) {
                ulonglong2 wa = wrow[cp * 5 + 0];   // w0 w1
                ulonglong2 wb = wrow[cp * 5 + 1];   // w2 w3
                ulonglong2 wc = wrow[cp * 5 + 2];   // w4 w5
                ulonglong2 wd = wrow[cp * 5 + 3];   // w6 w7
                ull we = reinterpret_cast<const ull*>(wrow)[cp * 10 + 8]; // w8
                // row oy0
                FMA2(accA[cp], t0, wa.x);
                FMA2(accA[cp], t1, wa.y);
                FMA2(accA[cp], t2, wb.x);
                FMA2(accA[cp], t3, wb.y);
                FMA2(accA[cp], t4, wc.x);
                FMA2(accA[cp], t5, wc.y);
                FMA2(accA[cp], t6, wd.x);
                FMA2(accA[cp], t7, wd.y);
                FMA2(accA[cp], t8, we);
                // row oy0+1 (shifted one row down)
                FMA2(accB[cp], t3, wa.x);
                FMA2(accB[cp], t4, wa.y);
                FMA2(accB[cp], t5, wb.x);
                FMA2(accB[cp], t6, wb.y);
                FMA2(accB[cp], t7, wc.x);
                FMA2(accB[cp], t8, wc.y);
                FMA2(accB[cp], t9, wd.x);
                FMA2(accB[cp], t10, wd.y);
                FMA2(accB[cp], t11, we);
            }
        }
        __syncthreads();
    }

    float* outB = out + batch * NC * chanStride + oy0 * Ww + ox;
#pragma unroll
    for (int cp = 0; cp < 8; cp++) {
        int gp = qz * 8 + cp;                 // global cout pair
        float b0 = bias[2 * gp], b1 = bias[2 * gp + 1];
        unsigned a_lo = (unsigned)(accA[cp] & 0xffffffffull);
        unsigned a_hi = (unsigned)(accA[cp] >> 32);
        unsigned b_lo = (unsigned)(accB[cp] & 0xffffffffull);
        unsigned b_hi = (unsigned)(accB[cp] >> 32);
        float v00 = __uint_as_float(a_lo) + b0;   // row0, cout even
        float v01 = __uint_as_float(a_hi) + b1;   // row0, cout odd
        float v10 = __uint_as_float(b_lo) + b0;   // row1, cout even
        float v11 = __uint_as_float(b_hi) + b1;   // row1, cout odd
        float* p0 = outB + (2 * gp) * chanStride;
        float* p1 = outB + (2 * gp + 1) * chanStride;
        p0[0]  = v00 > 0.f ? v00 : 0.f;
        p1[0]  = v01 > 0.f ? v01 : 0.f;
        p0[Ww] = v10 > 0.f ? v10 : 0.f;
        p1[Ww] = v11 > 0.f ? v11 : 0.f;
    }
}

// ---------------------------------------------------------------------------
// conv 3x3 SAME, 64 -> 1, +bias, ReLU (mask head)
// ---------------------------------------------------------------------------
__global__ __launch_bounds__(256)
void conv1out(const float* __restrict__ in, const float* __restrict__ wgt,
              const float* __restrict__ bias, float* __restrict__ out,
              int Hh, int Ww)
{
    __shared__ float s_in[8 * 324];
    __shared__ float sw[576];

    const int tilesX = Ww >> 4;
    const int tX = blockIdx.x % tilesX;
    const int tY = blockIdx.x / tilesX;
    const int batch = blockIdx.y;
    const int tid = threadIdx.x;
    const int px = tid & 15, py = tid >> 4;
    const int ox = (tX << 4) + px, oy = (tY << 4) + py;
    const int chanStride = Hh * Ww;
    const float* inB = in + batch * NC * chanStride;

    for (int idx = tid; idx < 576; idx += 256) sw[idx] = wgt[idx];

    float acc = 0.f;
    for (int cc = 0; cc < 8; cc++) {
        for (int idx = tid; idx < 8 * 324; idx += 256) {
            int ci = idx / 324;
            int r  = idx - ci * 324;
            int ry = r / 18, rx = r - ry * 18;
            int gy = (tY << 4) + ry - 1;
            int gx = (tX << 4) + rx - 1;
            float v = 0.f;
            if ((unsigned)gy < (unsigned)Hh && (unsigned)gx < (unsigned)Ww)
                v = inB[(cc * 8 + ci) * chanStride + gy * Ww + gx];
            s_in[idx] = v;
        }
        __syncthreads();
#pragma unroll
        for (int ci = 0; ci < 8; ci++) {
            const float* si = s_in + ci * 324 + py * 18 + px;
            const float* w9 = sw + (cc * 8 + ci) * 9;
            acc += w9[0] * si[0]  + w9[1] * si[1]  + w9[2] * si[2]
                 + w9[3] * si[18] + w9[4] * si[19] + w9[5] * si[20]
                 + w9[6] * si[36] + w9[7] * si[37] + w9[8] * si[38];
        }
        __syncthreads();
    }
    float v = acc + bias[0];
    out[batch * chanStride + oy * Ww + ox] = v > 0.f ? v : 0.f;
}

// ---------------------------------------------------------------------------
// Stage 1: per-pixel softmax weight fields  g_wf[i][HW] (i=0..7 inst, 8=bg)
// ---------------------------------------------------------------------------
__global__ __launch_bounds__(256)
void wfield_k()
{
    const int p4 = blockIdx.x * 256 + threadIdx.x;
    const int base = p4 * 4;
    const int y = base >> 9;
    const int xb = base & 511;

    float4 wv[9];

#pragma unroll
    for (int j = 0; j < 4; j++) {
        const int x = xb + j;
        float m[8];
        bool uni = false;
        bool ins[8];
#pragma unroll
        for (int i = 0; i < 8; i++) {
            int xl = x - cL[i], yt = y - cT[i];
            bool in_i = ((unsigned)xl < (unsigned)cBW[i]) &&
                        ((unsigned)yt < (unsigned)cBH[i]);
            ins[i] = in_i;
            uni |= in_i;
            float mi = 0.f;
            if (in_i) {
                float sx = ((float)xl + 0.5f) * (128.f / (float)cBW[i]) - 0.5f;
                float sy = ((float)yt + 0.5f) * (128.f / (float)cBH[i]) - 0.5f;
                float fxf = floorf(sx), fyf = floorf(sy);
                float fx = sx - fxf, fy = sy - fyf;
                int x0 = (int)fxf, y0 = (int)fyf;
                int x0c = x0 < 0 ? 0 : x0;
                int x1c = (x0 + 1 > 127) ? 127 : (x0 + 1);
                int y0c = y0 < 0 ? 0 : y0;
                int y1c = (y0 + 1 > 127) ? 127 : (y0 + 1);
                const float* mp = g_imask + i * (IH * IW);
                float v00 = mp[y0c * 128 + x0c], v01 = mp[y0c * 128 + x1c];
                float v10 = mp[y1c * 128 + x0c], v11 = mp[y1c * 128 + x1c];
                mi = (1.f - fx) * (1.f - fy) * v00 + fx * (1.f - fy) * v01
                   + (1.f - fx) * fy * v10 + fx * fy * v11;
            }
            m[i] = mi;
        }
        float bgv = g_bgmask[base + j] + (uni ? 0.f : BIGV);
        float mx = bgv;
#pragma unroll
        for (int i = 0; i < 8; i++) mx = fmaxf(mx, m[i]);
        float ebg = expf(bgv - mx);
        float s = ebg;
        float e[8];
#pragma unroll
        for (int i = 0; i < 8; i++) { e[i] = expf(m[i] - mx); s += e[i]; }
        float inv = 1.f / s;
#pragma unroll
        for (int i = 0; i < 8; i++) (&wv[i].x)[j] = e[i] * inv;
        (&wv[8].x)[j] = ebg * inv;
    }

#pragma unroll
    for (int i = 0; i < 9; i++)
        reinterpret_cast<float4*>(g_wf + i * HW)[p4] = wv[i];
}

// ---------------------------------------------------------------------------
// Stage 2: horizontal bilinear resize 128x128 -> 128 x bw per channel
// ---------------------------------------------------------------------------
__global__ __launch_bounds__(128)
void hresize_k(const float* __restrict__ instf, int inst, int bw, float scale)
{
    __shared__ float srow[128];
    const int c  = blockIdx.x >> 7;
    const int sy = blockIdx.x & 127;
    const int tid = threadIdx.x;

    const float* src = instf + ((inst * 64 + c) * 128 + sy) * 128;
    if (tid < 32)
        reinterpret_cast<float4*>(srow)[tid] =
            reinterpret_cast<const float4*>(src)[tid];
    __syncthreads();

    float* dst = g_bg1 + cHOFF[inst] + (c * 128 + sy) * bw;
    const int nx = bw >> 2;
    for (int xg = tid; xg < nx; xg += 128) {
        float4 o;
#pragma unroll
        for (int j = 0; j < 4; j++) {
            int x = xg * 4 + j;
            float sx = ((float)x + 0.5f) * scale - 0.5f;
            float fxf = floorf(sx);
            float fx = sx - fxf;
            int x0 = (int)fxf;
            int x0c = x0 < 0 ? 0 : x0;
            int x1c = (x0 + 1 > 127) ? 127 : (x0 + 1);
            (&o.x)[j] = (1.f - fx) * srow[x0c] + fx * srow[x1c];
        }
        reinterpret_cast<float4*>(dst)[xg] = o;
    }
}

// ---------------------------------------------------------------------------
// Stage 3: out[c][px] = wbg*bg + sum_i wi * vlerp(htmp_i); float4 per thread.
// ---------------------------------------------------------------------------
__global__ __launch_bounds__(256)
void gather3(const float* __restrict__ bgf, float* __restrict__ out)
{
    const int gid = blockIdx.x * 256 + threadIdx.x;
    const int c  = gid >> 16;
    const int p4 = gid & 65535;
    const int base = p4 * 4;
    const int y = base >> 9;
    const int xb = base & 511;

    float4 bg4  = reinterpret_cast<const float4*>(bgf + c * HW)[p4];
    float4 wbg4 = reinterpret_cast<const float4*>(g_wf + 8 * HW)[p4];
    float4 acc;
    acc.x = wbg4.x * bg4.x;
    acc.y = wbg4.y * bg4.y;
    acc.z = wbg4.z * bg4.z;
    acc.w = wbg4.w * bg4.w;

#pragma unroll
    for (int i = 0; i < 8; i++) {
        int xl = xb - cL[i], yt = y - cT[i];
        if (((unsigned)xl < (unsigned)cBW[i]) && ((unsigned)yt < (unsigned)cBH[i])) {
            float4 wi4 = reinterpret_cast<const float4*>(g_wf + i * HW)[p4];
            float sy = ((float)yt + 0.5f) * (128.f / (float)cBH[i]) - 0.5f;
            float fyf = floorf(sy);
            float fy = sy - fyf;
            int y0 = (int)fyf;
            int y0c = y0 < 0 ? 0 : y0;
            int y1c = (y0 + 1 > 127) ? 127 : (y0 + 1);
            const float* hb = g_bg1 + cHOFF[i] + c * 128 * cBW[i];
            float4 r0 = *reinterpret_cast<const float4*>(hb + y0c * cBW[i] + xl);
            float4 r1 = *reinterpret_cast<const float4*>(hb + y1c * cBW[i] + xl);
            float g0 = 1.f - fy;
            acc.x += wi4.x * (g0 * r0.x + fy * r1.x);
            acc.y += wi4.y * (g0 * r0.y + fy * r1.y);
            acc.z += wi4.z * (g0 * r0.z + fy * r1.z);
            acc.w += wi4.w * (g0 * r0.w + fy * r1.w);
        }
    }

    reinterpret_cast<float4*>(out + c * HW)[p4] = acc;
}

// ---------------------------------------------------------------------------
// Launcher
// ---------------------------------------------------------------------------
extern "C" void kernel_launch(void* const* d_in, const int* in_sizes, int n_in,
                              void* d_out, int out_size)
{
    const float* instf = (const float*)d_in[0];
    const float* bgf   = (const float*)d_in[1];
    const float* iw1 = (const float*)d_in[2];
    const float* ib1 = (const float*)d_in[3];
    const float* iw2 = (const float*)d_in[4];
    const float* ib2 = (const float*)d_in[5];
    const float* iw3 = (const float*)d_in[6];
    const float* ib3 = (const float*)d_in[7];
    const float* bw1 = (const float*)d_in[8];
    const float* bb1 = (const float*)d_in[9];
    const float* bw2 = (const float*)d_in[10];
    const float* bb2 = (const float*)d_in[11];
    const float* bw3 = (const float*)d_in[12];
    const float* bb3 = (const float*)d_in[13];
    float* out = (float*)d_out;

    float *ga, *gb, *gim, *gbm;
    cudaGetSymbolAddress((void**)&ga,  g_bg1);
    cudaGetSymbolAddress((void**)&gb,  g_bg2);
    cudaGetSymbolAddress((void**)&gim, g_imask);
    cudaGetSymbolAddress((void**)&gbm, g_bgmask);

    const int PP = (64 * 32 * 10 + 255) / 256;

    // Instance branch: 8 x 128x128 -> tiles 8x4=32, z=4 cout quarters
    prepack <<<PP, 256>>>(iw1);
    conv64q <<<dim3(32, 8, 4), 256>>>(instf, ib1, ga, IH, IW);
    prepack <<<PP, 256>>>(iw2);
    conv64q <<<dim3(32, 8, 4), 256>>>(ga, ib2, gb, IH, IW);
    conv1out<<<dim3(64, 8), 256>>>(gb, iw3, ib3, gim, IH, IW);

    // Background branch: 512x512 -> tiles 32x16=512, z=4
    prepack <<<PP, 256>>>(bw1);
    conv64q <<<dim3(512, 1, 4), 256>>>(bgf, bb1, ga, HBG, WBG);
    prepack <<<PP, 256>>>(bw2);
    conv64q <<<dim3(512, 1, 4), 256>>>(ga, bb2, gb, HBG, WBG);
    conv1out<<<dim3(1024, 1), 256>>>(gb, bw3, bb3, gbm, HBG, WBG);

    // Epilogue stages
    wfield_k<<<HW / 4 / 256, 256>>>();
    const int hbw[8] = {256, 192, 320, 128, 384, 256, 160, 224};
    for (int i = 0; i < 8; i++)
        hresize_k<<<64 * 128, 128>>>(instf, i, hbw[i], 128.f / (float)hbw[i]);
    gather3<<<64 * (HW / 4) / 256, 256>>>(bgf, out);
}

// round 8
// speedup vs baseline: 1.5127x; 1.1486x over previous
#include <cuda_runtime.h>
#include <math.h>

#define HBG 512
#define WBG 512
#define HW  (HBG * WBG)
#define IH  128
#define IW  128
#define NC  64
#define NINST 8
#define BIGV 100000.0f

typedef unsigned long long ull;

// Scratch (device globals — allocation-free rule).
__device__ float  g_bg1[NC * HW];             // bg L1 out; later htmp slabs
__device__ float  g_bg2[NC * HW];             // bg L2 out
__device__ float  g_i1[NINST * NC * IH * IW]; // inst L1 out
__device__ float  g_i2[NINST * NC * IH * IW]; // inst L2 out
__device__ float  g_imask[NINST * IH * IW];
__device__ float  g_bgmask[HW];
__device__ float  g_wf[9 * HW];
__device__ float2 g_wpk[4 * 64 * 32 * 10];    // [set][ci][cp][k]

#define FMA2(d, a, b) asm("fma.rn.f32x2 %0, %1, %2, %3;" : "=l"(d) : "l"(a), "l"(b), "l"(d))

__device__ __constant__ int cL[8]  = {0, 64, 128, 300, 64, 200, 32, 256};
__device__ __constant__ int cT[8]  = {0, 32, 256, 300, 128, 100, 256, 320};
__device__ __constant__ int cBW[8] = {256, 192, 320, 128, 384, 256, 160, 224};
__device__ __constant__ int cBH[8] = {256, 320, 192, 128, 256, 384, 224, 160};
__device__ __constant__ int cHOFF[8] = {0, 2097152, 3670016, 6291456,
                                        7340032, 10485760, 12582912, 13893632};

// ---------------------------------------------------------------------------
// Pre-pack OIHW weights into co-pair float2 layout, per set.
// ---------------------------------------------------------------------------
__global__ void prepack(const float* __restrict__ w, int set)
{
    int idx = blockIdx.x * 256 + threadIdx.x;
    if (idx >= 64 * 32 * 10) return;
    int k  = idx % 10;
    int cp = (idx / 10) % 32;
    int ci = idx / 320;
    float2 v = make_float2(0.f, 0.f);
    if (k < 9) {
        v.x = w[((2 * cp)     * 64 + ci) * 9 + k];
        v.y = w[((2 * cp + 1) * 64 + ci) * 9 + k];
    }
    g_wpk[set * 20480 + idx] = v;
}

// ---------------------------------------------------------------------------
// conv 3x3 SAME 64->64 (+bias, ReLU) — f32x2, 2 px/thread, 16 couts/block,
// MERGED grid: blocks [0,2048) = bg 512x512, [2048,3072) = 8 inst 128x128.
// ---------------------------------------------------------------------------
__global__ __launch_bounds__(256, 2)
void conv64r(const float* __restrict__ inI, const float* __restrict__ inBg,
             float* __restrict__ outI, float* __restrict__ outBg,
             const float* __restrict__ biasI, const float* __restrict__ biasBg,
             int wsI, int wsBg)
{
    __shared__ __align__(16) float2 s_in2[8 * 612];   // 8 ci x 34x18 halo, (p,p)
    __shared__ __align__(16) float2 s_wp [8 * 80];    // 8 ci x 8 pairs x 10

    const int b = blockIdx.x;
    int W, tX, tY, batch, qz, wset;
    const float* in; float* out; const float* bias;
    if (b < 2048) {
        W = 512; qz = b >> 9;
        int t = b & 511; tX = t & 31; tY = t >> 5; batch = 0;
        in = inBg; out = outBg; bias = biasBg; wset = wsBg;
    } else {
        int b2 = b - 2048;
        W = 128; qz = b2 >> 8;
        int r = b2 & 255; batch = r >> 5;
        int t = r & 31; tX = t & 7; tY = t >> 3;
        in = inI; out = outI; bias = biasI; wset = wsI;
    }
    const int H = W;
    const int tid = threadIdx.x;
    const int px  = tid & 15;
    const int pyh = tid >> 4;
    const int ox = (tX << 4) + px;
    const int oy0 = (tY << 5) + (pyh << 1);
    const int chanStride = H * W;
    const float* inB = in + batch * NC * chanStride;

    ull accA[8], accB[8];
#pragma unroll
    for (int i = 0; i < 8; i++) { accA[i] = 0ull; accB[i] = 0ull; }

    for (int cc = 0; cc < 8; cc++) {
        for (int idx = tid; idx < 8 * 612; idx += 256) {
            int ci = idx / 612;
            int r  = idx - ci * 612;
            int ry = r / 18, rx = r - ry * 18;
            int gy = (tY << 5) + ry - 1;
            int gx = (tX << 4) + rx - 1;
            float v = 0.f;
            if ((unsigned)gy < (unsigned)H && (unsigned)gx < (unsigned)W)
                v = inB[(cc * 8 + ci) * chanStride + gy * W + gx];
            s_in2[idx] = make_float2(v, v);
        }
        for (int idx = tid; idx < 320; idx += 256) {   // 320 float4
            int ci = idx / 40;
            int r  = idx - ci * 40;
            reinterpret_cast<float4*>(s_wp)[idx] =
                reinterpret_cast<const float4*>(g_wpk)[wset * 10240 +
                    (cc * 8 + ci) * 160 + qz * 40 + r];
        }
        __syncthreads();

#pragma unroll 1
        for (int ci = 0; ci < 8; ci++) {
            const float2* si = s_in2 + ci * 612 + (pyh << 1) * 18 + px;
            ull t0  = *reinterpret_cast<const ull*>(si + 0);
            ull t1  = *reinterpret_cast<const ull*>(si + 1);
            ull t2  = *reinterpret_cast<const ull*>(si + 2);
            ull t3  = *reinterpret_cast<const ull*>(si + 18);
            ull t4  = *reinterpret_cast<const ull*>(si + 19);
            ull t5  = *reinterpret_cast<const ull*>(si + 20);
            ull t6  = *reinterpret_cast<const ull*>(si + 36);
            ull t7  = *reinterpret_cast<const ull*>(si + 37);
            ull t8  = *reinterpret_cast<const ull*>(si + 38);
            ull t9  = *reinterpret_cast<const ull*>(si + 54);
            ull t10 = *reinterpret_cast<const ull*>(si + 55);
            ull t11 = *reinterpret_cast<const ull*>(si + 56);
            const ulonglong2* wrow =
                reinterpret_cast<const ulonglong2*>(s_wp + ci * 80);
            // register double-buffer of weights across cp
            ulonglong2 wa = wrow[0], wb = wrow[1], wc = wrow[2], wd = wrow[3];
            ull we = reinterpret_cast<const ull*>(wrow)[8];
#pragma unroll
            for (int cp = 0; cp < 8; cp++) {
                ulonglong2 na, nb, nc, nd; ull ne;
                if (cp < 7) {
                    na = wrow[(cp + 1) * 5 + 0];
                    nb = wrow[(cp + 1) * 5 + 1];
                    nc = wrow[(cp + 1) * 5 + 2];
                    nd = wrow[(cp + 1) * 5 + 3];
                    ne = reinterpret_cast<const ull*>(wrow)[(cp + 1) * 10 + 8];
                } else { na = wa; nb = wb; nc = wc; nd = wd; ne = we; }
                FMA2(accA[cp], t0, wa.x);
                FMA2(accA[cp], t1, wa.y);
                FMA2(accA[cp], t2, wb.x);
                FMA2(accA[cp], t3, wb.y);
                FMA2(accA[cp], t4, wc.x);
                FMA2(accA[cp], t5, wc.y);
                FMA2(accA[cp], t6, wd.x);
                FMA2(accA[cp], t7, wd.y);
                FMA2(accA[cp], t8, we);
                FMA2(accB[cp], t3, wa.x);
                FMA2(accB[cp], t4, wa.y);
                FMA2(accB[cp], t5, wb.x);
                FMA2(accB[cp], t6, wb.y);
                FMA2(accB[cp], t7, wc.x);
                FMA2(accB[cp], t8, wc.y);
                FMA2(accB[cp], t9, wd.x);
                FMA2(accB[cp], t10, wd.y);
                FMA2(accB[cp], t11, we);
                wa = na; wb = nb; wc = nc; wd = nd; we = ne;
            }
        }
        __syncthreads();
    }

    float* outB = out + batch * NC * chanStride + oy0 * W + ox;
#pragma unroll
    for (int cp = 0; cp < 8; cp++) {
        int gp = qz * 8 + cp;
        float b0 = bias[2 * gp], b1 = bias[2 * gp + 1];
        unsigned a_lo = (unsigned)(accA[cp] & 0xffffffffull);
        unsigned a_hi = (unsigned)(accA[cp] >> 32);
        unsigned b_lo = (unsigned)(accB[cp] & 0xffffffffull);
        unsigned b_hi = (unsigned)(accB[cp] >> 32);
        float v00 = __uint_as_float(a_lo) + b0;
        float v01 = __uint_as_float(a_hi) + b1;
        float v10 = __uint_as_float(b_lo) + b0;
        float v11 = __uint_as_float(b_hi) + b1;
        float* p0 = outB + (2 * gp) * chanStride;
        float* p1 = outB + (2 * gp + 1) * chanStride;
        p0[0] = v00 > 0.f ? v00 : 0.f;
        p1[0] = v01 > 0.f ? v01 : 0.f;
        p0[W] = v10 > 0.f ? v10 : 0.f;
        p1[W] = v11 > 0.f ? v11 : 0.f;
    }
}

// ---------------------------------------------------------------------------
// MERGED mask head: conv 3x3 64->1 (+bias, ReLU).
// blocks [0,1024) = bg (32x32 tiles), [1024,1536) = inst (8 img x 64 tiles).
// ---------------------------------------------------------------------------
__global__ __launch_bounds__(256)
void conv1outM(const float* __restrict__ inI, const float* __restrict__ inBg,
               const float* __restrict__ wI, const float* __restrict__ bI,
               const float* __restrict__ wBg, const float* __restrict__ bBg)
{
    __shared__ float s_in[8 * 324];
    __shared__ float sw[576];

    const int b = blockIdx.x;
    int W, tX, tY, batch;
    const float* in; const float* wgt; const float* bias; float* out;
    if (b < 1024) {
        W = 512; tX = b & 31; tY = b >> 5; batch = 0;
        in = inBg; wgt = wBg; bias = bBg; out = g_bgmask;
    } else {
        int b2 = b - 1024;
        W = 128; batch = b2 >> 6;
        int t = b2 & 63; tX = t & 7; tY = t >> 3;
        in = inI; wgt = wI; bias = bI; out = g_imask;
    }
    const int H = W;
    const int tid = threadIdx.x;
    const int px = tid & 15, py = tid >> 4;
    const int ox = (tX << 4) + px, oy = (tY << 4) + py;
    const int chs = H * W;
    const float* inB = in + batch * NC * chs;

    for (int idx = tid; idx < 576; idx += 256) sw[idx] = wgt[idx];

    float acc = 0.f;
    for (int cc = 0; cc < 8; cc++) {
        for (int idx = tid; idx < 8 * 324; idx += 256) {
            int ci = idx / 324, r = idx - ci * 324;
            int ry = r / 18, rx = r - ry * 18;
            int gy = (tY << 4) + ry - 1, gx = (tX << 4) + rx - 1;
            float v = 0.f;
            if ((unsigned)gy < (unsigned)H && (unsigned)gx < (unsigned)W)
                v = inB[(cc * 8 + ci) * chs + gy * W + gx];
            s_in[idx] = v;
        }
        __syncthreads();
#pragma unroll
        for (int ci = 0; ci < 8; ci++) {
            const float* si = s_in + ci * 324 + py * 18 + px;
            const float* w9 = sw + (cc * 8 + ci) * 9;
            acc += w9[0]*si[0] + w9[1]*si[1] + w9[2]*si[2]
                 + w9[3]*si[18] + w9[4]*si[19] + w9[5]*si[20]
                 + w9[6]*si[36] + w9[7]*si[37] + w9[8]*si[38];
        }
        __syncthreads();
    }
    float v = acc + bias[0];
    out[batch * chs + oy * W + ox] = v > 0.f ? v : 0.f;
}

// ---------------------------------------------------------------------------
// Epilogue stage 1: softmax weight fields
// ---------------------------------------------------------------------------
__global__ __launch_bounds__(256)
void wfield_k()
{
    const int p4 = blockIdx.x * 256 + threadIdx.x;
    const int base = p4 * 4, y = base >> 9, xb = base & 511;
    float4 wv[9];
#pragma unroll
    for (int j = 0; j < 4; j++) {
        const int x = xb + j;
        float m[8]; bool uni = false;
#pragma unroll
        for (int i = 0; i < 8; i++) {
            int xl = x - cL[i], yt = y - cT[i];
            bool in_i = ((unsigned)xl < (unsigned)cBW[i]) && ((unsigned)yt < (unsigned)cBH[i]);
            uni |= in_i;
            float mi = 0.f;
            if (in_i) {
                float sx = ((float)xl + 0.5f) * (128.f / (float)cBW[i]) - 0.5f;
                float sy = ((float)yt + 0.5f) * (128.f / (float)cBH[i]) - 0.5f;
                float fxf = floorf(sx), fyf = floorf(sy);
                float fx = sx - fxf, fy = sy - fyf;
                int x0 = (int)fxf, y0 = (int)fyf;
                int x0c = x0 < 0 ? 0 : x0, x1c = (x0 + 1 > 127) ? 127 : (x0 + 1);
                int y0c = y0 < 0 ? 0 : y0, y1c = (y0 + 1 > 127) ? 127 : (y0 + 1);
                const float* mp = g_imask + i * (IH * IW);
                float v00 = mp[y0c*128+x0c], v01 = mp[y0c*128+x1c];
                float v10 = mp[y1c*128+x0c], v11 = mp[y1c*128+x1c];
                mi = (1.f-fx)*(1.f-fy)*v00 + fx*(1.f-fy)*v01 + (1.f-fx)*fy*v10 + fx*fy*v11;
            }
            m[i] = mi;
        }
        float bgv = g_bgmask[base + j] + (uni ? 0.f : BIGV);
        float mx = bgv;
#pragma unroll
        for (int i = 0; i < 8; i++) mx = fmaxf(mx, m[i]);
        float ebg = expf(bgv - mx), s = ebg, e[8];
#pragma unroll
        for (int i = 0; i < 8; i++) { e[i] = expf(m[i] - mx); s += e[i]; }
        float inv = 1.f / s;
#pragma unroll
        for (int i = 0; i < 8; i++) (&wv[i].x)[j] = e[i] * inv;
        (&wv[8].x)[j] = ebg * inv;
    }
#pragma unroll
    for (int i = 0; i < 9; i++)
        reinterpret_cast<float4*>(g_wf + i * HW)[p4] = wv[i];
}

// ---------------------------------------------------------------------------
// Epilogue stage 2: horizontal bilinear resize into htmp slabs (g_bg1)
// ---------------------------------------------------------------------------
__global__ __launch_bounds__(128)
void hresize_k(const float* __restrict__ instf, int inst, int bw, float scale)
{
    __shared__ float srow[128];
    const int c = blockIdx.x >> 7, sy = blockIdx.x & 127, tid = threadIdx.x;
    const float* src = instf + ((inst * 64 + c) * 128 + sy) * 128;
    if (tid < 32)
        reinterpret_cast<float4*>(srow)[tid] = reinterpret_cast<const float4*>(src)[tid];
    __syncthreads();
    float* dst = g_bg1 + cHOFF[inst] + (c * 128 + sy) * bw;
    for (int xg = tid; xg < (bw >> 2); xg += 128) {
        float4 o;
#pragma unroll
        for (int j = 0; j < 4; j++) {
            int x = xg * 4 + j;
            float sx = ((float)x + 0.5f) * scale - 0.5f;
            float fxf = floorf(sx), fx = sx - fxf;
            int x0 = (int)fxf;
            int x0c = x0 < 0 ? 0 : x0, x1c = (x0 + 1 > 127) ? 127 : (x0 + 1);
            (&o.x)[j] = (1.f - fx) * srow[x0c] + fx * srow[x1c];
        }
        reinterpret_cast<float4*>(dst)[xg] = o;
    }
}

// ---------------------------------------------------------------------------
// Epilogue stage 3: vertical lerp + weighted sum + bg
// ---------------------------------------------------------------------------
__global__ __launch_bounds__(256)
void gather3(const float* __restrict__ bgf, float* __restrict__ out)
{
    const int gid = blockIdx.x * 256 + threadIdx.x;
    const int c = gid >> 16, p4 = gid & 65535;
    const int base = p4 * 4, y = base >> 9, xb = base & 511;
    float4 bg4  = reinterpret_cast<const float4*>(bgf + c * HW)[p4];
    float4 wbg4 = reinterpret_cast<const float4*>(g_wf + 8 * HW)[p4];
    float4 acc = make_float4(wbg4.x*bg4.x, wbg4.y*bg4.y, wbg4.z*bg4.z, wbg4.w*bg4.w);
#pragma unroll
    for (int i = 0; i < 8; i++) {
        int xl = xb - cL[i], yt = y - cT[i];
        if (((unsigned)xl < (unsigned)cBW[i]) && ((unsigned)yt < (unsigned)cBH[i])) {
            float4 wi4 = reinterpret_cast<const float4*>(g_wf + i * HW)[p4];
            float sy = ((float)yt + 0.5f) * (128.f / (float)cBH[i]) - 0.5f;
            float fyf = floorf(sy), fy = sy - fyf;
            int y0 = (int)fyf;
            int y0c = y0 < 0 ? 0 : y0, y1c = (y0 + 1 > 127) ? 127 : (y0 + 1);
            const float* hb = g_bg1 + cHOFF[i] + c * 128 * cBW[i];
            float4 r0 = *reinterpret_cast<const float4*>(hb + y0c * cBW[i] + xl);
            float4 r1 = *reinterpret_cast<const float4*>(hb + y1c * cBW[i] + xl);
            float g0 = 1.f - fy;
            acc.x += wi4.x * (g0*r0.x + fy*r1.x);
            acc.y += wi4.y * (g0*r0.y + fy*r1.y);
            acc.z += wi4.z * (g0*r0.z + fy*r1.z);
            acc.w += wi4.w * (g0*r0.w + fy*r1.w);
        }
    }
    reinterpret_cast<float4*>(out + c * HW)[p4] = acc;
}

// ---------------------------------------------------------------------------
extern "C" void kernel_launch(void* const* d_in, const int* in_sizes, int n_in,
                              void* d_out, int out_size)
{
    const float* instf = (const float*)d_in[0];
    const float* bgf   = (const float*)d_in[1];
    const float* iw1 = (const float*)d_in[2];
    const float* ib1 = (const float*)d_in[3];
    const float* iw2 = (const float*)d_in[4];
    const float* ib2 = (const float*)d_in[5];
    const float* iw3 = (const float*)d_in[6];
    const float* ib3 = (const float*)d_in[7];
    const float* bw1 = (const float*)d_in[8];
    const float* bb1 = (const float*)d_in[9];
    const float* bw2 = (const float*)d_in[10];
    const float* bb2 = (const float*)d_in[11];
    const float* bw3 = (const float*)d_in[12];
    const float* bb3 = (const float*)d_in[13];
    float* out = (float*)d_out;

    float *ga, *gb, *gi1, *gi2;
    cudaGetSymbolAddress((void**)&ga,  g_bg1);
    cudaGetSymbolAddress((void**)&gb,  g_bg2);
    cudaGetSymbolAddress((void**)&gi1, g_i1);
    cudaGetSymbolAddress((void**)&gi2, g_i2);

    const int PP = (64 * 32 * 10 + 255) / 256;

    // Pack all 4 weight sets: 0=iw1, 1=iw2, 2=bw1, 3=bw2
    prepack<<<PP, 256>>>(iw1, 0);
    prepack<<<PP, 256>>>(iw2, 1);
    prepack<<<PP, 256>>>(bw1, 2);
    prepack<<<PP, 256>>>(bw2, 3);

    // Merged conv layers (bg + inst in one grid)
    conv64r<<<3072, 256>>>(instf, bgf, gi1, ga, ib1, bb1, 0, 2);
    conv64r<<<3072, 256>>>(gi1,   ga,  gi2, gb, ib2, bb2, 1, 3);

    // Merged mask heads
    conv1outM<<<1536, 256>>>(gi2, gb, iw3, ib3, bw3, bb3);

    // Epilogue
    wfield_k<<<HW / 4 / 256, 256>>>();
    const int hbw[8] = {256, 192, 320, 128, 384, 256, 160, 224};
    for (int i = 0; i < 8; i++)
        hresize_k<<<64 * 128, 128>>>(instf, i, hbw[i], 128.f / (float)hbw[i]);
    gather3<<<64 * (HW / 4) / 256, 256>>>(bgf, out);
}